// round 1
// baseline (speedup 1.0000x reference)
#include <cuda_runtime.h>
#include <stdint.h>

// Problem-shape constants (fixed for this dataset)
#define ND_MAX 50000
#define NP_MAX 50000

// ---------------- scratch layout (floats) ----------------
// Zero-initialized region first (aggregation targets + degrees), then
// non-zeroed intermediates.
constexpr size_t S_AGG_DDI = 0;                                   // [ND,128]
constexpr size_t S_AGG_DPI = S_AGG_DDI + (size_t)ND_MAX * 128;    // [NP,128]
constexpr size_t S_AGG_PPI = S_AGG_DPI + (size_t)NP_MAX * 128;    // [NP,128]
constexpr size_t S_ACC_DDI = S_AGG_PPI + (size_t)NP_MAX * 128;    // [ND,64]
constexpr size_t S_ACC_DPI = S_ACC_DDI + (size_t)ND_MAX * 64;     // [NP,64]
constexpr size_t S_ACC_PPI = S_ACC_DPI + (size_t)NP_MAX * 64;     // [NP,64]
constexpr size_t S_DEG_DDI = S_ACC_PPI + (size_t)NP_MAX * 64;     // [ND]
constexpr size_t S_DEG_DPI = S_DEG_DDI + ND_MAX;                  // [NP]
constexpr size_t S_DEG_PPI = S_DEG_DPI + NP_MAX;                  // [NP]
constexpr size_t S_ZERO_END = S_DEG_PPI + NP_MAX;                 // 28,950,000 floats
constexpr size_t S_HD    = S_ZERO_END;                            // [ND,128]
constexpr size_t S_HP    = S_HD + (size_t)ND_MAX * 128;           // [NP,128]
constexpr size_t S_T_DDI = S_HP + (size_t)NP_MAX * 128;           // [ND,64]
constexpr size_t S_T_DPI = S_T_DDI + (size_t)ND_MAX * 64;         // [ND,64]
constexpr size_t S_T_PPI = S_T_DPI + (size_t)ND_MAX * 64;         // [NP,64]
constexpr size_t S_TOTAL = S_T_PPI + (size_t)NP_MAX * 64;

static_assert(S_ZERO_END % 4 == 0, "zero region must be float4-aligned");

__device__ float g_scratch[S_TOTAL];

// ---------------- kernels ----------------

__global__ void k_zero(size_t n4) {
    size_t i = (size_t)blockIdx.x * blockDim.x + threadIdx.x;
    size_t stride = (size_t)gridDim.x * blockDim.x;
    float4* p = reinterpret_cast<float4*>(g_scratch);
    float4 z = make_float4(0.f, 0.f, 0.f, 0.f);
    for (; i < n4; i += stride) p[i] = z;
}

__global__ void k_degree(const int* __restrict__ dd, int ed,
                         const int* __restrict__ dp, int ep,
                         const int* __restrict__ pp, int eq,
                         float* __restrict__ degd,
                         float* __restrict__ degp1,
                         float* __restrict__ degp2) {
    int i = blockIdx.x * blockDim.x + threadIdx.x;
    int stride = gridDim.x * blockDim.x;
    for (int j = i; j < ed; j += stride) atomicAdd(&degd[dd[j]], 1.0f);
    for (int j = i; j < ep; j += stride) atomicAdd(&degp1[dp[j]], 1.0f);
    for (int j = i; j < eq; j += stride) atomicAdd(&degp2[pp[j]], 1.0f);
}

// One warp per edge; lane l handles feature dims [4l, 4l+4). 128-dim payload.
__global__ void k_scatter128(const float* __restrict__ x,
                             const int* __restrict__ src,
                             const int* __restrict__ dst,
                             float* __restrict__ agg, int E) {
    int t = blockIdx.x * blockDim.x + threadIdx.x;
    int e = t >> 5;
    if (e >= E) return;
    int lane = t & 31;
    int s = __ldg(src + e);
    int d = __ldg(dst + e);
    float4 v = *reinterpret_cast<const float4*>(x + (size_t)s * 128 + lane * 4);
    float* o = agg + (size_t)d * 128 + lane * 4;
    atomicAdd(o + 0, v.x);
    atomicAdd(o + 1, v.y);
    atomicAdd(o + 2, v.z);
    atomicAdd(o + 3, v.w);
}

// 16 lanes per edge; lane l handles dims [4l, 4l+4). 64-dim payload.
__global__ void k_scatter64(const float* __restrict__ x,
                            const int* __restrict__ src,
                            const int* __restrict__ dst,
                            float* __restrict__ agg, int E) {
    int t = blockIdx.x * blockDim.x + threadIdx.x;
    int e = t >> 4;
    if (e >= E) return;
    int lane = t & 15;
    int s = __ldg(src + e);
    int d = __ldg(dst + e);
    float4 v = *reinterpret_cast<const float4*>(x + (size_t)s * 64 + lane * 4);
    float* o = agg + (size_t)d * 64 + lane * 4;
    atomicAdd(o + 0, v.x);
    atomicAdd(o + 1, v.y);
    atomicAdd(o + 2, v.z);
    atomicAdd(o + 3, v.w);
}

// out[r, :] = (A[r, :] / max(deg[r],1)) @ W[128x128] + b
// blockDim = 128 (thread j = output column), 16 rows per block.
__global__ void k_gemm_norm_128(const float* __restrict__ A,
                                const float* __restrict__ deg,
                                const float* __restrict__ W,
                                const float* __restrict__ b,
                                float* __restrict__ out, int n) {
    __shared__ float xs[16][128];
    int j = threadIdx.x;
    int row0 = blockIdx.x * 16;
#pragma unroll
    for (int r = 0; r < 16; r++) {
        int rr = row0 + r;
        float v = 0.f;
        if (rr < n) {
            float inv = 1.0f / fmaxf(deg[rr], 1.0f);
            v = A[(size_t)rr * 128 + j] * inv;
        }
        xs[r][j] = v;
    }
    __syncthreads();
    float acc[16];
#pragma unroll
    for (int r = 0; r < 16; r++) acc[r] = 0.f;
    for (int k = 0; k < 128; k++) {
        float wv = __ldg(W + k * 128 + j);
#pragma unroll
        for (int r = 0; r < 16; r++) acc[r] += xs[r][k] * wv;
    }
    float bb = b[j];
#pragma unroll
    for (int r = 0; r < 16; r++) {
        int rr = row0 + r;
        if (rr < n) out[(size_t)rr * 128 + j] = acc[r] + bb;
    }
}

// h_p[r,:] = norm(A1[r])@W1 + norm(A2[r])@W2 + b1 + b2  (dual-relation dst)
__global__ void k_gemm_norm_128_dual(const float* __restrict__ A1,
                                     const float* __restrict__ deg1,
                                     const float* __restrict__ W1,
                                     const float* __restrict__ A2,
                                     const float* __restrict__ deg2,
                                     const float* __restrict__ W2,
                                     const float* __restrict__ b1,
                                     const float* __restrict__ b2,
                                     float* __restrict__ out, int n) {
    __shared__ float xs1[16][128];
    __shared__ float xs2[16][128];
    int j = threadIdx.x;
    int row0 = blockIdx.x * 16;
#pragma unroll
    for (int r = 0; r < 16; r++) {
        int rr = row0 + r;
        float v1 = 0.f, v2 = 0.f;
        if (rr < n) {
            v1 = A1[(size_t)rr * 128 + j] * (1.0f / fmaxf(deg1[rr], 1.0f));
            v2 = A2[(size_t)rr * 128 + j] * (1.0f / fmaxf(deg2[rr], 1.0f));
        }
        xs1[r][j] = v1;
        xs2[r][j] = v2;
    }
    __syncthreads();
    float acc[16];
#pragma unroll
    for (int r = 0; r < 16; r++) acc[r] = 0.f;
    for (int k = 0; k < 128; k++) {
        float w1 = __ldg(W1 + k * 128 + j);
        float w2 = __ldg(W2 + k * 128 + j);
#pragma unroll
        for (int r = 0; r < 16; r++) acc[r] += xs1[r][k] * w1 + xs2[r][k] * w2;
    }
    float bb = b1[j] + b2[j];
#pragma unroll
    for (int r = 0; r < 16; r++) {
        int rr = row0 + r;
        if (rr < n) out[(size_t)rr * 128 + j] = acc[r] + bb;
    }
}

// Dual-output [nx128]@[128x64]: ta = H@Wa, tb = H@Wb  (no bias — bias added
// post-normalization in k_combine). blockDim = 128; threads 0-63 -> Wa/ta,
// 64-127 -> Wb/tb. 16 rows per block.
__global__ void k_gemm2_dual(const float* __restrict__ H,
                             const float* __restrict__ Wa,
                             const float* __restrict__ Wb,
                             float* __restrict__ ta,
                             float* __restrict__ tb, int n) {
    __shared__ float xs[16][128];
    int tid = threadIdx.x;
    int row0 = blockIdx.x * 16;
#pragma unroll
    for (int r = 0; r < 16; r++) {
        int rr = row0 + r;
        xs[r][tid] = (rr < n) ? H[(size_t)rr * 128 + tid] : 0.f;
    }
    __syncthreads();
    const float* W = (tid < 64) ? Wa : Wb;
    float* o = (tid < 64) ? ta : tb;
    int c = tid & 63;
    float acc[16];
#pragma unroll
    for (int r = 0; r < 16; r++) acc[r] = 0.f;
    for (int k = 0; k < 128; k++) {
        float wv = __ldg(W + k * 64 + c);
#pragma unroll
        for (int r = 0; r < 16; r++) acc[r] += xs[r][k] * wv;
    }
#pragma unroll
    for (int r = 0; r < 16; r++) {
        int rr = row0 + r;
        if (rr < n) o[(size_t)rr * 64 + c] = acc[r];
    }
}

// Single-output [nx128]@[128x64]: blockDim = 128, 32 rows per block;
// thread group g = tid>>6 handles rows [g*16, g*16+16), column c = tid&63.
__global__ void k_gemm2_single(const float* __restrict__ H,
                               const float* __restrict__ W,
                               float* __restrict__ t, int n) {
    __shared__ float xs[32][128];
    int tid = threadIdx.x;
    int row0 = blockIdx.x * 32;
#pragma unroll
    for (int r = 0; r < 32; r++) {
        int rr = row0 + r;
        xs[r][tid] = (rr < n) ? H[(size_t)rr * 128 + tid] : 0.f;
    }
    __syncthreads();
    int g = tid >> 6;
    int c = tid & 63;
    int rbase = g * 16;
    float acc[16];
#pragma unroll
    for (int r = 0; r < 16; r++) acc[r] = 0.f;
    for (int k = 0; k < 128; k++) {
        float wv = __ldg(W + k * 64 + c);
#pragma unroll
        for (int r = 0; r < 16; r++) acc[r] += xs[rbase + r][k] * wv;
    }
#pragma unroll
    for (int r = 0; r < 16; r++) {
        int rr = row0 + rbase + r;
        if (rr < n) t[(size_t)rr * 64 + c] = acc[r];
    }
}

// Final normalize + bias + concat into output.
__global__ void k_combine(float* __restrict__ out,
                          const float* __restrict__ acc_ddi,
                          const float* __restrict__ acc_dpi,
                          const float* __restrict__ acc_ppi,
                          const float* __restrict__ deg_ddi,
                          const float* __restrict__ deg_dpi,
                          const float* __restrict__ deg_ppi,
                          const float* __restrict__ b2_ddi,
                          const float* __restrict__ b2_dpi,
                          const float* __restrict__ b2_ppi,
                          int nd, int np) {
    int total = (nd + np) * 64;
    int i = blockIdx.x * blockDim.x + threadIdx.x;
    int stride = gridDim.x * blockDim.x;
    int ndrug = nd * 64;
    for (; i < total; i += stride) {
        if (i < ndrug) {
            int r = i >> 6, c = i & 63;
            out[i] = acc_ddi[i] / fmaxf(deg_ddi[r], 1.0f) + b2_ddi[c];
        } else {
            int i2 = i - ndrug;
            int r = i2 >> 6, c = i2 & 63;
            out[i] = acc_dpi[i2] / fmaxf(deg_dpi[r], 1.0f) + b2_dpi[c]
                   + acc_ppi[i2] / fmaxf(deg_ppi[r], 1.0f) + b2_ppi[c];
        }
    }
}

// ---------------- host launcher ----------------

static float* scratch_ptr() {
    static float* p = nullptr;
    if (!p) cudaGetSymbolAddress((void**)&p, g_scratch);
    return p;
}

static inline int cdiv(long long a, long long b) { return (int)((a + b - 1) / b); }

extern "C" void kernel_launch(void* const* d_in, const int* in_sizes, int n_in,
                              void* d_out, int out_size) {
    const float* x_drug = (const float*)d_in[0];
    const float* x_prot = (const float*)d_in[1];
    const int* src_ddi = (const int*)d_in[2];
    const int* dst_ddi = (const int*)d_in[3];
    const int* src_dpi = (const int*)d_in[4];
    const int* dst_dpi = (const int*)d_in[5];
    const int* src_ppi = (const int*)d_in[6];
    const int* dst_ppi = (const int*)d_in[7];
    const float* W1_ddi = (const float*)d_in[8];
    const float* b1_ddi = (const float*)d_in[9];
    const float* W1_dpi = (const float*)d_in[10];
    const float* b1_dpi = (const float*)d_in[11];
    const float* W1_ppi = (const float*)d_in[12];
    const float* b1_ppi = (const float*)d_in[13];
    const float* W2_ddi = (const float*)d_in[14];
    const float* b2_ddi = (const float*)d_in[15];
    const float* W2_dpi = (const float*)d_in[16];
    const float* b2_dpi = (const float*)d_in[17];
    const float* W2_ppi = (const float*)d_in[18];
    const float* b2_ppi = (const float*)d_in[19];
    float* out = (float*)d_out;

    int nd = in_sizes[0] / 128;
    int np = in_sizes[1] / 128;
    int ed = in_sizes[2];
    int ep = in_sizes[4];
    int eq = in_sizes[6];

    float* S = scratch_ptr();
    float* agg_ddi = S + S_AGG_DDI;
    float* agg_dpi = S + S_AGG_DPI;
    float* agg_ppi = S + S_AGG_PPI;
    float* acc_ddi = S + S_ACC_DDI;
    float* acc_dpi = S + S_ACC_DPI;
    float* acc_ppi = S + S_ACC_PPI;
    float* deg_ddi = S + S_DEG_DDI;
    float* deg_dpi = S + S_DEG_DPI;
    float* deg_ppi = S + S_DEG_PPI;
    float* h_d  = S + S_HD;
    float* h_p  = S + S_HP;
    float* t_ddi = S + S_T_DDI;
    float* t_dpi = S + S_T_DPI;
    float* t_ppi = S + S_T_PPI;

    // 1) zero aggregation targets + degrees
    {
        size_t n4 = S_ZERO_END / 4;
        k_zero<<<cdiv((long long)n4, 256), 256>>>(n4);
    }

    // 2) degrees (reused by both layers)
    {
        int emax = ed > ep ? ed : ep;
        if (eq > emax) emax = eq;
        k_degree<<<cdiv(emax, 256), 256>>>(dst_ddi, ed, dst_dpi, ep, dst_ppi, eq,
                                           deg_ddi, deg_dpi, deg_ppi);
    }

    // 3) layer-1 aggregation of RAW features (aggregate-then-transform)
    k_scatter128<<<cdiv((long long)ed * 32, 256), 256>>>(x_drug, src_ddi, dst_ddi, agg_ddi, ed);
    k_scatter128<<<cdiv((long long)ep * 32, 256), 256>>>(x_drug, src_dpi, dst_dpi, agg_dpi, ep);
    k_scatter128<<<cdiv((long long)eq * 32, 256), 256>>>(x_prot, src_ppi, dst_ppi, agg_ppi, eq);

    // 4) layer-1 GEMMs (normalize inline)
    k_gemm_norm_128<<<cdiv(nd, 16), 128>>>(agg_ddi, deg_ddi, W1_ddi, b1_ddi, h_d, nd);
    k_gemm_norm_128_dual<<<cdiv(np, 16), 128>>>(agg_dpi, deg_dpi, W1_dpi,
                                                agg_ppi, deg_ppi, W1_ppi,
                                                b1_dpi, b1_ppi, h_p, np);

    // 5) layer-2 transforms (transform-then-aggregate: 64-dim scatter payload)
    k_gemm2_dual<<<cdiv(nd, 16), 128>>>(h_d, W2_ddi, W2_dpi, t_ddi, t_dpi, nd);
    k_gemm2_single<<<cdiv(np, 32), 128>>>(h_p, W2_ppi, t_ppi, np);

    // 6) layer-2 aggregation (64-dim)
    k_scatter64<<<cdiv((long long)ed * 16, 256), 256>>>(t_ddi, src_ddi, dst_ddi, acc_ddi, ed);
    k_scatter64<<<cdiv((long long)ep * 16, 256), 256>>>(t_dpi, src_dpi, dst_dpi, acc_dpi, ep);
    k_scatter64<<<cdiv((long long)eq * 16, 256), 256>>>(t_ppi, src_ppi, dst_ppi, acc_ppi, eq);

    // 7) normalize + bias + concat
    k_combine<<<cdiv((long long)(nd + np) * 64, 256), 256>>>(
        out, acc_ddi, acc_dpi, acc_ppi, deg_ddi, deg_dpi, deg_ppi,
        b2_ddi, b2_dpi, b2_ppi, nd, np);
}

// round 2
// speedup vs baseline: 1.7511x; 1.7511x over previous
#include <cuda_runtime.h>
#include <stdint.h>

#define NMAX 50000
#define EMAX 600000

// ---------------- CSR scratch (ints) ----------------
__device__ int g_rowptr[3][NMAX + 1];   // counts during build, then exclusive prefix
__device__ int g_cursor[3][NMAX];       // fill cursors
__device__ int g_esrc[3][EMAX];         // edge src ids grouped by dst

// ---------------- float scratch ----------------
constexpr size_t F_AGG_DDI = 0;                                    // [ND,128] normalized sums
constexpr size_t F_AGG_DPI = F_AGG_DDI + (size_t)NMAX * 128;
constexpr size_t F_AGG_PPI = F_AGG_DPI + (size_t)NMAX * 128;
constexpr size_t F_HD      = F_AGG_PPI + (size_t)NMAX * 128;       // [ND,128]
constexpr size_t F_HP      = F_HD      + (size_t)NMAX * 128;       // [NP,128]
constexpr size_t F_T_DDI   = F_HP      + (size_t)NMAX * 128;       // [ND,64]
constexpr size_t F_T_DPI   = F_T_DDI   + (size_t)NMAX * 64;
constexpr size_t F_T_PPI   = F_T_DPI   + (size_t)NMAX * 64;
constexpr size_t F_ACC_DDI = F_T_PPI   + (size_t)NMAX * 64;        // [ND,64] normalized
constexpr size_t F_ACC_DPI = F_ACC_DDI + (size_t)NMAX * 64;
constexpr size_t F_ACC_PPI = F_ACC_DPI + (size_t)NMAX * 64;
constexpr size_t F_TOTAL   = F_ACC_PPI + (size_t)NMAX * 64;

__device__ float g_fs[F_TOTAL];

// ---------------- CSR build ----------------

__global__ void k_zero_counts() {
    int i = blockIdx.x * blockDim.x + threadIdx.x;
    int total = 3 * (NMAX + 1);
    int stride = gridDim.x * blockDim.x;
    int* p = &g_rowptr[0][0];
    for (; i < total; i += stride) p[i] = 0;
}

__global__ void k_count(const int* __restrict__ d0, int e0,
                        const int* __restrict__ d1, int e1,
                        const int* __restrict__ d2, int e2) {
    int i = blockIdx.x * blockDim.x + threadIdx.x;
    int stride = gridDim.x * blockDim.x;
    for (int j = i; j < e0; j += stride) atomicAdd(&g_rowptr[0][d0[j]], 1);
    for (int j = i; j < e1; j += stride) atomicAdd(&g_rowptr[1][d1[j]], 1);
    for (int j = i; j < e2; j += stride) atomicAdd(&g_rowptr[2][d2[j]], 1);
}

// One block (1024 threads) per relation: exclusive scan of counts in-place,
// also fills cursor copy and rowptr[n] total.
__global__ void k_scan(int n0, int n1, int n2) {
    int rel = blockIdx.x;
    int n = (rel == 0) ? n0 : ((rel == 1) ? n1 : n2);
    int* cnt = g_rowptr[rel];
    int* cur = g_cursor[rel];
    __shared__ int sh[1024];
    int tid = threadIdx.x;
    int chunk = (n + 1023) >> 10;
    int lo = tid * chunk;
    int hi = lo + chunk;
    if (hi > n) hi = n;
    int tsum = 0;
    for (int i = lo; i < hi; i++) tsum += cnt[i];
    sh[tid] = tsum;
    __syncthreads();
    for (int off = 1; off < 1024; off <<= 1) {
        int v = (tid >= off) ? sh[tid - off] : 0;
        __syncthreads();
        sh[tid] += v;
        __syncthreads();
    }
    int run = (tid > 0) ? sh[tid - 1] : 0;
    for (int i = lo; i < hi; i++) {
        int c = cnt[i];
        cnt[i] = run;
        cur[i] = run;
        run += c;
    }
    if (tid == 0) cnt[n] = sh[1023];
}

__global__ void k_fill(int rel, const int* __restrict__ src,
                       const int* __restrict__ dst, int E) {
    int i = blockIdx.x * blockDim.x + threadIdx.x;
    int stride = gridDim.x * blockDim.x;
    int* cur = g_cursor[rel];
    int* es = g_esrc[rel];
    for (int e = i; e < E; e += stride) {
        int d = dst[e];
        int pos = atomicAdd(&cur[d], 1);
        es[pos] = src[e];
    }
}

// ---------------- atomic-free gathers ----------------

// Warp per dst node; lane l covers dims [4l, 4l+4). Writes normalized mean.
__global__ void k_gather128(int rel, const float* __restrict__ x,
                            float* __restrict__ out, int n) {
    int t = blockIdx.x * blockDim.x + threadIdx.x;
    int node = t >> 5;
    if (node >= n) return;
    int lane = t & 31;
    const int* ptr = g_rowptr[rel];
    const int* es = g_esrc[rel];
    int beg = ptr[node], end = ptr[node + 1];
    float4 acc = make_float4(0.f, 0.f, 0.f, 0.f);
    int e = beg;
    for (; e + 1 < end; e += 2) {
        int s0 = __ldg(es + e);
        int s1 = __ldg(es + e + 1);
        float4 v0 = __ldg(reinterpret_cast<const float4*>(x + (size_t)s0 * 128) + lane);
        float4 v1 = __ldg(reinterpret_cast<const float4*>(x + (size_t)s1 * 128) + lane);
        acc.x += v0.x + v1.x;
        acc.y += v0.y + v1.y;
        acc.z += v0.z + v1.z;
        acc.w += v0.w + v1.w;
    }
    if (e < end) {
        int s = __ldg(es + e);
        float4 v = __ldg(reinterpret_cast<const float4*>(x + (size_t)s * 128) + lane);
        acc.x += v.x; acc.y += v.y; acc.z += v.z; acc.w += v.w;
    }
    float inv = 1.0f / fmaxf((float)(end - beg), 1.0f);
    float4 o = make_float4(acc.x * inv, acc.y * inv, acc.z * inv, acc.w * inv);
    *(reinterpret_cast<float4*>(out + (size_t)node * 128) + lane) = o;
}

// Warp per dst node; lane l covers dims [2l, 2l+2). Writes normalized mean.
__global__ void k_gather64(int rel, const float* __restrict__ x,
                           float* __restrict__ out, int n) {
    int t = blockIdx.x * blockDim.x + threadIdx.x;
    int node = t >> 5;
    if (node >= n) return;
    int lane = t & 31;
    const int* ptr = g_rowptr[rel];
    const int* es = g_esrc[rel];
    int beg = ptr[node], end = ptr[node + 1];
    float2 acc = make_float2(0.f, 0.f);
    int e = beg;
    for (; e + 1 < end; e += 2) {
        int s0 = __ldg(es + e);
        int s1 = __ldg(es + e + 1);
        float2 v0 = __ldg(reinterpret_cast<const float2*>(x + (size_t)s0 * 64) + lane);
        float2 v1 = __ldg(reinterpret_cast<const float2*>(x + (size_t)s1 * 64) + lane);
        acc.x += v0.x + v1.x;
        acc.y += v0.y + v1.y;
    }
    if (e < end) {
        int s = __ldg(es + e);
        float2 v = __ldg(reinterpret_cast<const float2*>(x + (size_t)s * 64) + lane);
        acc.x += v.x; acc.y += v.y;
    }
    float inv = 1.0f / fmaxf((float)(end - beg), 1.0f);
    *(reinterpret_cast<float2*>(out + (size_t)node * 64) + lane) =
        make_float2(acc.x * inv, acc.y * inv);
}

// ---------------- GEMMs (inputs already normalized) ----------------

// out[r,:] = A[r,:] @ W[128x128] + b ; blockDim=128, 16 rows/block
__global__ void k_gemm1_single(const float* __restrict__ A,
                               const float* __restrict__ W,
                               const float* __restrict__ b,
                               float* __restrict__ out, int n) {
    __shared__ float xs[16][128];
    int j = threadIdx.x;
    int row0 = blockIdx.x * 16;
#pragma unroll
    for (int r = 0; r < 16; r++) {
        int rr = row0 + r;
        xs[r][j] = (rr < n) ? A[(size_t)rr * 128 + j] : 0.f;
    }
    __syncthreads();
    float acc[16];
#pragma unroll
    for (int r = 0; r < 16; r++) acc[r] = 0.f;
    for (int k = 0; k < 128; k++) {
        float wv = __ldg(W + k * 128 + j);
#pragma unroll
        for (int r = 0; r < 16; r++) acc[r] += xs[r][k] * wv;
    }
    float bb = b[j];
#pragma unroll
    for (int r = 0; r < 16; r++) {
        int rr = row0 + r;
        if (rr < n) out[(size_t)rr * 128 + j] = acc[r] + bb;
    }
}

// out = A1@W1 + A2@W2 + b1 + b2
__global__ void k_gemm1_dual(const float* __restrict__ A1,
                             const float* __restrict__ W1,
                             const float* __restrict__ A2,
                             const float* __restrict__ W2,
                             const float* __restrict__ b1,
                             const float* __restrict__ b2,
                             float* __restrict__ out, int n) {
    __shared__ float xs1[16][128];
    __shared__ float xs2[16][128];
    int j = threadIdx.x;
    int row0 = blockIdx.x * 16;
#pragma unroll
    for (int r = 0; r < 16; r++) {
        int rr = row0 + r;
        xs1[r][j] = (rr < n) ? A1[(size_t)rr * 128 + j] : 0.f;
        xs2[r][j] = (rr < n) ? A2[(size_t)rr * 128 + j] : 0.f;
    }
    __syncthreads();
    float acc[16];
#pragma unroll
    for (int r = 0; r < 16; r++) acc[r] = 0.f;
    for (int k = 0; k < 128; k++) {
        float w1 = __ldg(W1 + k * 128 + j);
        float w2 = __ldg(W2 + k * 128 + j);
#pragma unroll
        for (int r = 0; r < 16; r++) acc[r] += xs1[r][k] * w1 + xs2[r][k] * w2;
    }
    float bb = b1[j] + b2[j];
#pragma unroll
    for (int r = 0; r < 16; r++) {
        int rr = row0 + r;
        if (rr < n) out[(size_t)rr * 128 + j] = acc[r] + bb;
    }
}

// ta = H@Wa, tb = H@Wb  (bias deferred to combine)
__global__ void k_gemm2_dual(const float* __restrict__ H,
                             const float* __restrict__ Wa,
                             const float* __restrict__ Wb,
                             float* __restrict__ ta,
                             float* __restrict__ tb, int n) {
    __shared__ float xs[16][128];
    int tid = threadIdx.x;
    int row0 = blockIdx.x * 16;
#pragma unroll
    for (int r = 0; r < 16; r++) {
        int rr = row0 + r;
        xs[r][tid] = (rr < n) ? H[(size_t)rr * 128 + tid] : 0.f;
    }
    __syncthreads();
    const float* W = (tid < 64) ? Wa : Wb;
    float* o = (tid < 64) ? ta : tb;
    int c = tid & 63;
    float acc[16];
#pragma unroll
    for (int r = 0; r < 16; r++) acc[r] = 0.f;
    for (int k = 0; k < 128; k++) {
        float wv = __ldg(W + k * 64 + c);
#pragma unroll
        for (int r = 0; r < 16; r++) acc[r] += xs[r][k] * wv;
    }
#pragma unroll
    for (int r = 0; r < 16; r++) {
        int rr = row0 + r;
        if (rr < n) o[(size_t)rr * 64 + c] = acc[r];
    }
}

__global__ void k_gemm2_single(const float* __restrict__ H,
                               const float* __restrict__ W,
                               float* __restrict__ t, int n) {
    __shared__ float xs[32][128];
    int tid = threadIdx.x;
    int row0 = blockIdx.x * 32;
#pragma unroll
    for (int r = 0; r < 32; r++) {
        int rr = row0 + r;
        xs[r][tid] = (rr < n) ? H[(size_t)rr * 128 + tid] : 0.f;
    }
    __syncthreads();
    int g = tid >> 6;
    int c = tid & 63;
    int rbase = g * 16;
    float acc[16];
#pragma unroll
    for (int r = 0; r < 16; r++) acc[r] = 0.f;
    for (int k = 0; k < 128; k++) {
        float wv = __ldg(W + k * 64 + c);
#pragma unroll
        for (int r = 0; r < 16; r++) acc[r] += xs[rbase + r][k] * wv;
    }
#pragma unroll
    for (int r = 0; r < 16; r++) {
        int rr = row0 + rbase + r;
        if (rr < n) t[(size_t)rr * 64 + c] = acc[r];
    }
}

// ---------------- final combine ----------------
__global__ void k_combine(float* __restrict__ out,
                          const float* __restrict__ acc_ddi,
                          const float* __restrict__ acc_dpi,
                          const float* __restrict__ acc_ppi,
                          const float* __restrict__ b2_ddi,
                          const float* __restrict__ b2_dpi,
                          const float* __restrict__ b2_ppi,
                          int nd, int np) {
    int total = (nd + np) * 64;
    int i = blockIdx.x * blockDim.x + threadIdx.x;
    int stride = gridDim.x * blockDim.x;
    int ndrug = nd * 64;
    for (; i < total; i += stride) {
        if (i < ndrug) {
            int c = i & 63;
            out[i] = acc_ddi[i] + b2_ddi[c];
        } else {
            int i2 = i - ndrug;
            int c = i2 & 63;
            out[i] = acc_dpi[i2] + acc_ppi[i2] + b2_dpi[c] + b2_ppi[c];
        }
    }
}

// ---------------- host launcher ----------------

static float* fs_ptr() {
    static float* p = nullptr;
    if (!p) cudaGetSymbolAddress((void**)&p, g_fs);
    return p;
}

static inline int cdiv(long long a, long long b) { return (int)((a + b - 1) / b); }

extern "C" void kernel_launch(void* const* d_in, const int* in_sizes, int n_in,
                              void* d_out, int out_size) {
    const float* x_drug = (const float*)d_in[0];
    const float* x_prot = (const float*)d_in[1];
    const int* src_ddi = (const int*)d_in[2];
    const int* dst_ddi = (const int*)d_in[3];
    const int* src_dpi = (const int*)d_in[4];
    const int* dst_dpi = (const int*)d_in[5];
    const int* src_ppi = (const int*)d_in[6];
    const int* dst_ppi = (const int*)d_in[7];
    const float* W1_ddi = (const float*)d_in[8];
    const float* b1_ddi = (const float*)d_in[9];
    const float* W1_dpi = (const float*)d_in[10];
    const float* b1_dpi = (const float*)d_in[11];
    const float* W1_ppi = (const float*)d_in[12];
    const float* b1_ppi = (const float*)d_in[13];
    const float* W2_ddi = (const float*)d_in[14];
    const float* b2_ddi = (const float*)d_in[15];
    const float* W2_dpi = (const float*)d_in[16];
    const float* b2_dpi = (const float*)d_in[17];
    const float* W2_ppi = (const float*)d_in[18];
    const float* b2_ppi = (const float*)d_in[19];
    float* out = (float*)d_out;

    int nd = in_sizes[0] / 128;
    int np = in_sizes[1] / 128;
    int ed = in_sizes[2];
    int ep = in_sizes[4];
    int eq = in_sizes[6];

    float* S = fs_ptr();
    float* agg_ddi = S + F_AGG_DDI;
    float* agg_dpi = S + F_AGG_DPI;
    float* agg_ppi = S + F_AGG_PPI;
    float* h_d   = S + F_HD;
    float* h_p   = S + F_HP;
    float* t_ddi = S + F_T_DDI;
    float* t_dpi = S + F_T_DPI;
    float* t_ppi = S + F_T_PPI;
    float* acc_ddi = S + F_ACC_DDI;
    float* acc_dpi = S + F_ACC_DPI;
    float* acc_ppi = S + F_ACC_PPI;

    // ---- CSR build (shared by both layers) ----
    k_zero_counts<<<cdiv(3 * (NMAX + 1), 256), 256>>>();
    {
        int emax = ed > ep ? ed : ep;
        if (eq > emax) emax = eq;
        k_count<<<cdiv(emax, 256), 256>>>(dst_ddi, ed, dst_dpi, ep, dst_ppi, eq);
    }
    k_scan<<<3, 1024>>>(nd, np, np);
    k_fill<<<cdiv(ed, 256), 256>>>(0, src_ddi, dst_ddi, ed);
    k_fill<<<cdiv(ep, 256), 256>>>(1, src_dpi, dst_dpi, ep);
    k_fill<<<cdiv(eq, 256), 256>>>(2, src_ppi, dst_ppi, eq);

    // ---- layer 1: gather raw features (normalized), then transform ----
    k_gather128<<<cdiv((long long)nd * 32, 256), 256>>>(0, x_drug, agg_ddi, nd);
    k_gather128<<<cdiv((long long)np * 32, 256), 256>>>(1, x_drug, agg_dpi, np);
    k_gather128<<<cdiv((long long)np * 32, 256), 256>>>(2, x_prot, agg_ppi, np);

    k_gemm1_single<<<cdiv(nd, 16), 128>>>(agg_ddi, W1_ddi, b1_ddi, h_d, nd);
    k_gemm1_dual<<<cdiv(np, 16), 128>>>(agg_dpi, W1_dpi, agg_ppi, W1_ppi,
                                        b1_dpi, b1_ppi, h_p, np);

    // ---- layer 2: transform first (64-dim payload), then gather ----
    k_gemm2_dual<<<cdiv(nd, 16), 128>>>(h_d, W2_ddi, W2_dpi, t_ddi, t_dpi, nd);
    k_gemm2_single<<<cdiv(np, 32), 128>>>(h_p, W2_ppi, t_ppi, np);

    k_gather64<<<cdiv((long long)nd * 32, 256), 256>>>(0, t_ddi, acc_ddi, nd);
    k_gather64<<<cdiv((long long)np * 32, 256), 256>>>(1, t_dpi, acc_dpi, np);
    k_gather64<<<cdiv((long long)np * 32, 256), 256>>>(2, t_ppi, acc_ppi, np);

    // ---- normalize + bias + concat ----
    k_combine<<<cdiv((long long)(nd + np) * 64, 256), 256>>>(
        out, acc_ddi, acc_dpi, acc_ppi, b2_ddi, b2_dpi, b2_ppi, nd, np);
}

// round 3
// speedup vs baseline: 2.2781x; 1.3010x over previous
#include <cuda_runtime.h>
#include <stdint.h>

#define NMAX 50000
#define EMAX 600000

// ---------------- CSR scratch (ints) ----------------
__device__ int g_rowptr[3][NMAX + 1];
__device__ int g_cursor[3][NMAX];
__device__ int g_esrc[3][EMAX];

// ---------------- float scratch ----------------
constexpr size_t F_AGG_DDI = 0;                                    // [ND,128]
constexpr size_t F_AGG_DPI = F_AGG_DDI + (size_t)NMAX * 128;
constexpr size_t F_AGG_PPI = F_AGG_DPI + (size_t)NMAX * 128;
constexpr size_t F_HD      = F_AGG_PPI + (size_t)NMAX * 128;       // [ND,128]
constexpr size_t F_HP      = F_HD      + (size_t)NMAX * 128;       // [NP,128]
constexpr size_t F_T_DDI   = F_HP      + (size_t)NMAX * 128;       // [ND,64]
constexpr size_t F_T_DPI   = F_T_DDI   + (size_t)NMAX * 64;
constexpr size_t F_T_PPI   = F_T_DPI   + (size_t)NMAX * 64;
constexpr size_t F_TOTAL   = F_T_PPI   + (size_t)NMAX * 64;

__device__ float g_fs[F_TOTAL];

// ---------------- packed f32x2 helper ----------------
__device__ __forceinline__ unsigned long long ffma2(unsigned long long a,
                                                    unsigned long long b,
                                                    unsigned long long c) {
    unsigned long long d;
    asm("fma.rn.f32x2 %0, %1, %2, %3;" : "=l"(d) : "l"(a), "l"(b), "l"(c));
    return d;
}
__device__ __forceinline__ unsigned long long pack2(float lo, float hi) {
    unsigned long long d;
    asm("mov.b64 %0, {%1, %2};" : "=l"(d) : "f"(lo), "f"(hi));
    return d;
}
__device__ __forceinline__ void unpack2(unsigned long long v, float& lo, float& hi) {
    asm("mov.b64 {%0, %1}, %2;" : "=f"(lo), "=f"(hi) : "l"(v));
}

// ---------------- CSR build ----------------

__global__ void k_zero_counts() {
    int i = blockIdx.x * blockDim.x + threadIdx.x;
    int total = 3 * (NMAX + 1);
    int stride = gridDim.x * blockDim.x;
    int* p = &g_rowptr[0][0];
    for (; i < total; i += stride) p[i] = 0;
}

__global__ void k_count(const int* __restrict__ d0, int e0,
                        const int* __restrict__ d1, int e1,
                        const int* __restrict__ d2, int e2) {
    int i = blockIdx.x * blockDim.x + threadIdx.x;
    int stride = gridDim.x * blockDim.x;
    for (int j = i; j < e0; j += stride) atomicAdd(&g_rowptr[0][__ldg(d0 + j)], 1);
    for (int j = i; j < e1; j += stride) atomicAdd(&g_rowptr[1][__ldg(d1 + j)], 1);
    for (int j = i; j < e2; j += stride) atomicAdd(&g_rowptr[2][__ldg(d2 + j)], 1);
}

__global__ void k_scan(int n0, int n1, int n2) {
    int rel = blockIdx.x;
    int n = (rel == 0) ? n0 : ((rel == 1) ? n1 : n2);
    int* cnt = g_rowptr[rel];
    int* cur = g_cursor[rel];
    __shared__ int sh[1024];
    int tid = threadIdx.x;
    int chunk = (n + 1023) >> 10;
    int lo = tid * chunk;
    int hi = lo + chunk;
    if (hi > n) hi = n;
    int tsum = 0;
    for (int i = lo; i < hi; i++) tsum += cnt[i];
    sh[tid] = tsum;
    __syncthreads();
    for (int off = 1; off < 1024; off <<= 1) {
        int v = (tid >= off) ? sh[tid - off] : 0;
        __syncthreads();
        sh[tid] += v;
        __syncthreads();
    }
    int run = (tid > 0) ? sh[tid - 1] : 0;
    for (int i = lo; i < hi; i++) {
        int c = cnt[i];
        cnt[i] = run;
        cur[i] = run;
        run += c;
    }
    if (tid == 0) cnt[n] = sh[1023];
}

// All three relations in one launch (grid segmented).
__global__ void k_fill3(const int* __restrict__ s0, const int* __restrict__ d0, int e0,
                        const int* __restrict__ s1, const int* __restrict__ d1, int e1,
                        const int* __restrict__ s2, const int* __restrict__ d2, int e2) {
    int i = blockIdx.x * blockDim.x + threadIdx.x;
    int stride = gridDim.x * blockDim.x;
    for (int e = i; e < e0; e += stride) {
        int pos = atomicAdd(&g_cursor[0][__ldg(d0 + e)], 1);
        g_esrc[0][pos] = __ldg(s0 + e);
    }
    for (int e = i; e < e1; e += stride) {
        int pos = atomicAdd(&g_cursor[1][__ldg(d1 + e)], 1);
        g_esrc[1][pos] = __ldg(s1 + e);
    }
    for (int e = i; e < e2; e += stride) {
        int pos = atomicAdd(&g_cursor[2][__ldg(d2 + e)], 1);
        g_esrc[2][pos] = __ldg(s2 + e);
    }
}

// ---------------- gathers (atomic-free, unroll-4) ----------------

// Warp per dst node; lane covers dims [4l,4l+4). Mean over in-edges.
__global__ void k_gather128(int rel, const float* __restrict__ x,
                            float* __restrict__ out, int n) {
    int t = blockIdx.x * blockDim.x + threadIdx.x;
    int node = t >> 5;
    if (node >= n) return;
    int lane = t & 31;
    const int* ptr = g_rowptr[rel];
    const int* es = g_esrc[rel];
    int beg = ptr[node], end = ptr[node + 1];
    float4 a0 = make_float4(0.f, 0.f, 0.f, 0.f);
    float4 a1 = make_float4(0.f, 0.f, 0.f, 0.f);
    int e = beg;
    for (; e + 3 < end; e += 4) {
        int s0 = __ldg(es + e);
        int s1 = __ldg(es + e + 1);
        int s2 = __ldg(es + e + 2);
        int s3 = __ldg(es + e + 3);
        float4 v0 = __ldg(reinterpret_cast<const float4*>(x + (size_t)s0 * 128) + lane);
        float4 v1 = __ldg(reinterpret_cast<const float4*>(x + (size_t)s1 * 128) + lane);
        float4 v2 = __ldg(reinterpret_cast<const float4*>(x + (size_t)s2 * 128) + lane);
        float4 v3 = __ldg(reinterpret_cast<const float4*>(x + (size_t)s3 * 128) + lane);
        a0.x += v0.x + v1.x; a0.y += v0.y + v1.y;
        a0.z += v0.z + v1.z; a0.w += v0.w + v1.w;
        a1.x += v2.x + v3.x; a1.y += v2.y + v3.y;
        a1.z += v2.z + v3.z; a1.w += v2.w + v3.w;
    }
    for (; e < end; e++) {
        int s = __ldg(es + e);
        float4 v = __ldg(reinterpret_cast<const float4*>(x + (size_t)s * 128) + lane);
        a0.x += v.x; a0.y += v.y; a0.z += v.z; a0.w += v.w;
    }
    float inv = 1.0f / fmaxf((float)(end - beg), 1.0f);
    float4 o = make_float4((a0.x + a1.x) * inv, (a0.y + a1.y) * inv,
                           (a0.z + a1.z) * inv, (a0.w + a1.w) * inv);
    *(reinterpret_cast<float4*>(out + (size_t)node * 128) + lane) = o;
}

// Gather 64-dim mean for node via rel CSR. Returns float2 for dims (2l, 2l+1).
__device__ __forceinline__ float2 gather64_node(int rel, const float* __restrict__ x,
                                                int node, int lane) {
    const int* ptr = g_rowptr[rel];
    const int* es = g_esrc[rel];
    int beg = ptr[node], end = ptr[node + 1];
    float2 a0 = make_float2(0.f, 0.f);
    float2 a1 = make_float2(0.f, 0.f);
    int e = beg;
    for (; e + 3 < end; e += 4) {
        int s0 = __ldg(es + e);
        int s1 = __ldg(es + e + 1);
        int s2 = __ldg(es + e + 2);
        int s3 = __ldg(es + e + 3);
        float2 v0 = __ldg(reinterpret_cast<const float2*>(x + (size_t)s0 * 64) + lane);
        float2 v1 = __ldg(reinterpret_cast<const float2*>(x + (size_t)s1 * 64) + lane);
        float2 v2 = __ldg(reinterpret_cast<const float2*>(x + (size_t)s2 * 64) + lane);
        float2 v3 = __ldg(reinterpret_cast<const float2*>(x + (size_t)s3 * 64) + lane);
        a0.x += v0.x + v1.x; a0.y += v0.y + v1.y;
        a1.x += v2.x + v3.x; a1.y += v2.y + v3.y;
    }
    for (; e < end; e++) {
        int s = __ldg(es + e);
        float2 v = __ldg(reinterpret_cast<const float2*>(x + (size_t)s * 64) + lane);
        a0.x += v.x; a0.y += v.y;
    }
    float inv = 1.0f / fmaxf((float)(end - beg), 1.0f);
    return make_float2((a0.x + a1.x) * inv, (a0.y + a1.y) * inv);
}

// Drug output: out[node] = mean_ddi(t_ddi) + b2_ddi
__global__ void k_out_drug(const float* __restrict__ t_ddi,
                           const float* __restrict__ b2_ddi,
                           float* __restrict__ out, int nd) {
    int t = blockIdx.x * blockDim.x + threadIdx.x;
    int node = t >> 5;
    if (node >= nd) return;
    int lane = t & 31;
    float2 m = gather64_node(0, t_ddi, node, lane);
    float2 bb = __ldg(reinterpret_cast<const float2*>(b2_ddi) + lane);
    *(reinterpret_cast<float2*>(out + (size_t)node * 64) + lane) =
        make_float2(m.x + bb.x, m.y + bb.y);
}

// Protein output: out[nd+node] = mean_dpi(t_dpi) + mean_ppi(t_ppi) + b2_dpi + b2_ppi
__global__ void k_out_prot(const float* __restrict__ t_dpi,
                           const float* __restrict__ t_ppi,
                           const float* __restrict__ b2_dpi,
                           const float* __restrict__ b2_ppi,
                           float* __restrict__ out, int nd, int np) {
    int t = blockIdx.x * blockDim.x + threadIdx.x;
    int node = t >> 5;
    if (node >= np) return;
    int lane = t & 31;
    float2 m1 = gather64_node(1, t_dpi, node, lane);
    float2 m2 = gather64_node(2, t_ppi, node, lane);
    float2 ba = __ldg(reinterpret_cast<const float2*>(b2_dpi) + lane);
    float2 bb = __ldg(reinterpret_cast<const float2*>(b2_ppi) + lane);
    *(reinterpret_cast<float2*>(out + (size_t)(nd + node) * 64) + lane) =
        make_float2(m1.x + m2.x + ba.x + bb.x, m1.y + m2.y + ba.y + bb.y);
}

// ---------------- GEMMs (packed f32x2) ----------------

// out[r,:] = A[r,:] @ W[128x128] + b ; blockDim=128, 16 rows/block.
// smem xs[k][p] packs rows (row0+p, row0+p+8) at feature k.
__global__ void k_gemm1_single(const float* __restrict__ A,
                               const float* __restrict__ W,
                               const float* __restrict__ b,
                               float* __restrict__ out, int n) {
    __shared__ float2 xs[128][9];
    int j = threadIdx.x;
    int row0 = blockIdx.x * 16;
#pragma unroll
    for (int p = 0; p < 8; p++) {
        int r0 = row0 + p, r1 = row0 + p + 8;
        float v0 = (r0 < n) ? A[(size_t)r0 * 128 + j] : 0.f;
        float v1 = (r1 < n) ? A[(size_t)r1 * 128 + j] : 0.f;
        xs[j][p] = make_float2(v0, v1);
    }
    __syncthreads();
    unsigned long long acc[8];
#pragma unroll
    for (int p = 0; p < 8; p++) acc[p] = 0ull;
    for (int k = 0; k < 128; k++) {
        unsigned long long wv = pack2(__ldg(W + k * 128 + j), __ldg(W + k * 128 + j));
        const unsigned long long* row = reinterpret_cast<const unsigned long long*>(&xs[k][0]);
#pragma unroll
        for (int p = 0; p < 8; p++) acc[p] = ffma2(row[p], wv, acc[p]);
    }
    float bb = __ldg(b + j);
#pragma unroll
    for (int p = 0; p < 8; p++) {
        float lo, hi;
        unpack2(acc[p], lo, hi);
        int r0 = row0 + p, r1 = row0 + p + 8;
        if (r0 < n) out[(size_t)r0 * 128 + j] = lo + bb;
        if (r1 < n) out[(size_t)r1 * 128 + j] = hi + bb;
    }
}

// out = A1@W1 + A2@W2 + b1 + b2
__global__ void k_gemm1_dual(const float* __restrict__ A1,
                             const float* __restrict__ W1,
                             const float* __restrict__ A2,
                             const float* __restrict__ W2,
                             const float* __restrict__ b1,
                             const float* __restrict__ b2,
                             float* __restrict__ out, int n) {
    __shared__ float2 xs1[128][9];
    __shared__ float2 xs2[128][9];
    int j = threadIdx.x;
    int row0 = blockIdx.x * 16;
#pragma unroll
    for (int p = 0; p < 8; p++) {
        int r0 = row0 + p, r1 = row0 + p + 8;
        float a0 = (r0 < n) ? A1[(size_t)r0 * 128 + j] : 0.f;
        float a1 = (r1 < n) ? A1[(size_t)r1 * 128 + j] : 0.f;
        float c0 = (r0 < n) ? A2[(size_t)r0 * 128 + j] : 0.f;
        float c1 = (r1 < n) ? A2[(size_t)r1 * 128 + j] : 0.f;
        xs1[j][p] = make_float2(a0, a1);
        xs2[j][p] = make_float2(c0, c1);
    }
    __syncthreads();
    unsigned long long acc[8];
#pragma unroll
    for (int p = 0; p < 8; p++) acc[p] = 0ull;
    for (int k = 0; k < 128; k++) {
        float w1 = __ldg(W1 + k * 128 + j);
        float w2 = __ldg(W2 + k * 128 + j);
        unsigned long long wv1 = pack2(w1, w1);
        unsigned long long wv2 = pack2(w2, w2);
        const unsigned long long* r1p = reinterpret_cast<const unsigned long long*>(&xs1[k][0]);
        const unsigned long long* r2p = reinterpret_cast<const unsigned long long*>(&xs2[k][0]);
#pragma unroll
        for (int p = 0; p < 8; p++) {
            acc[p] = ffma2(r1p[p], wv1, acc[p]);
            acc[p] = ffma2(r2p[p], wv2, acc[p]);
        }
    }
    float bb = __ldg(b1 + j) + __ldg(b2 + j);
#pragma unroll
    for (int p = 0; p < 8; p++) {
        float lo, hi;
        unpack2(acc[p], lo, hi);
        int r0 = row0 + p, r1 = row0 + p + 8;
        if (r0 < n) out[(size_t)r0 * 128 + j] = lo + bb;
        if (r1 < n) out[(size_t)r1 * 128 + j] = hi + bb;
    }
}

// ta = H@Wa, tb = H@Wb (no bias). blockDim=128: tid<64 -> Wa/ta, else Wb/tb.
__global__ void k_gemm2_dual(const float* __restrict__ H,
                             const float* __restrict__ Wa,
                             const float* __restrict__ Wb,
                             float* __restrict__ ta,
                             float* __restrict__ tb, int n) {
    __shared__ float2 xs[128][9];
    int tid = threadIdx.x;
    int row0 = blockIdx.x * 16;
#pragma unroll
    for (int p = 0; p < 8; p++) {
        int r0 = row0 + p, r1 = row0 + p + 8;
        float v0 = (r0 < n) ? H[(size_t)r0 * 128 + tid] : 0.f;
        float v1 = (r1 < n) ? H[(size_t)r1 * 128 + tid] : 0.f;
        xs[tid][p] = make_float2(v0, v1);
    }
    __syncthreads();
    const float* W = (tid < 64) ? Wa : Wb;
    float* o = (tid < 64) ? ta : tb;
    int c = tid & 63;
    unsigned long long acc[8];
#pragma unroll
    for (int p = 0; p < 8; p++) acc[p] = 0ull;
    for (int k = 0; k < 128; k++) {
        float wv = __ldg(W + k * 64 + c);
        unsigned long long wv2 = pack2(wv, wv);
        const unsigned long long* row = reinterpret_cast<const unsigned long long*>(&xs[k][0]);
#pragma unroll
        for (int p = 0; p < 8; p++) acc[p] = ffma2(row[p], wv2, acc[p]);
    }
#pragma unroll
    for (int p = 0; p < 8; p++) {
        float lo, hi;
        unpack2(acc[p], lo, hi);
        int r0 = row0 + p, r1 = row0 + p + 8;
        if (r0 < n) o[(size_t)r0 * 64 + c] = lo;
        if (r1 < n) o[(size_t)r1 * 64 + c] = hi;
    }
}

// t = H@W (no bias). blockDim=128, 32 rows/block, two 16-row groups.
__global__ void k_gemm2_single(const float* __restrict__ H,
                               const float* __restrict__ W,
                               float* __restrict__ t, int n) {
    __shared__ float2 xs[128][2][9];
    int tid = threadIdx.x;
    int row0 = blockIdx.x * 32;
#pragma unroll
    for (int g = 0; g < 2; g++) {
#pragma unroll
        for (int p = 0; p < 8; p++) {
            int r0 = row0 + g * 16 + p, r1 = row0 + g * 16 + p + 8;
            float v0 = (r0 < n) ? H[(size_t)r0 * 128 + tid] : 0.f;
            float v1 = (r1 < n) ? H[(size_t)r1 * 128 + tid] : 0.f;
            xs[tid][g][p] = make_float2(v0, v1);
        }
    }
    __syncthreads();
    int g = tid >> 6;
    int c = tid & 63;
    unsigned long long acc[8];
#pragma unroll
    for (int p = 0; p < 8; p++) acc[p] = 0ull;
    for (int k = 0; k < 128; k++) {
        float wv = __ldg(W + k * 64 + c);
        unsigned long long wv2 = pack2(wv, wv);
        const unsigned long long* row = reinterpret_cast<const unsigned long long*>(&xs[k][g][0]);
#pragma unroll
        for (int p = 0; p < 8; p++) acc[p] = ffma2(row[p], wv2, acc[p]);
    }
#pragma unroll
    for (int p = 0; p < 8; p++) {
        float lo, hi;
        unpack2(acc[p], lo, hi);
        int r0 = row0 + g * 16 + p, r1 = row0 + g * 16 + p + 8;
        if (r0 < n) t[(size_t)r0 * 64 + c] = lo;
        if (r1 < n) t[(size_t)r1 * 64 + c] = hi;
    }
}

// ---------------- host launcher ----------------

static float* fs_ptr() {
    static float* p = nullptr;
    if (!p) cudaGetSymbolAddress((void**)&p, g_fs);
    return p;
}

static inline int cdiv(long long a, long long b) { return (int)((a + b - 1) / b); }

extern "C" void kernel_launch(void* const* d_in, const int* in_sizes, int n_in,
                              void* d_out, int out_size) {
    const float* x_drug = (const float*)d_in[0];
    const float* x_prot = (const float*)d_in[1];
    const int* src_ddi = (const int*)d_in[2];
    const int* dst_ddi = (const int*)d_in[3];
    const int* src_dpi = (const int*)d_in[4];
    const int* dst_dpi = (const int*)d_in[5];
    const int* src_ppi = (const int*)d_in[6];
    const int* dst_ppi = (const int*)d_in[7];
    const float* W1_ddi = (const float*)d_in[8];
    const float* b1_ddi = (const float*)d_in[9];
    const float* W1_dpi = (const float*)d_in[10];
    const float* b1_dpi = (const float*)d_in[11];
    const float* W1_ppi = (const float*)d_in[12];
    const float* b1_ppi = (const float*)d_in[13];
    const float* W2_ddi = (const float*)d_in[14];
    const float* b2_ddi = (const float*)d_in[15];
    const float* W2_dpi = (const float*)d_in[16];
    const float* b2_dpi = (const float*)d_in[17];
    const float* W2_ppi = (const float*)d_in[18];
    const float* b2_ppi = (const float*)d_in[19];
    float* out = (float*)d_out;

    int nd = in_sizes[0] / 128;
    int np = in_sizes[1] / 128;
    int ed = in_sizes[2];
    int ep = in_sizes[4];
    int eq = in_sizes[6];

    float* S = fs_ptr();
    float* agg_ddi = S + F_AGG_DDI;
    float* agg_dpi = S + F_AGG_DPI;
    float* agg_ppi = S + F_AGG_PPI;
    float* h_d   = S + F_HD;
    float* h_p   = S + F_HP;
    float* t_ddi = S + F_T_DDI;
    float* t_dpi = S + F_T_DPI;
    float* t_ppi = S + F_T_PPI;

    // ---- CSR build (shared by both layers) ----
    k_zero_counts<<<cdiv(3 * (NMAX + 1), 256), 256>>>();
    {
        int emax = ed > ep ? ed : ep;
        if (eq > emax) emax = eq;
        k_count<<<cdiv(emax, 256), 256>>>(dst_ddi, ed, dst_dpi, ep, dst_ppi, eq);
    }
    k_scan<<<3, 1024>>>(nd, np, np);
    {
        int emax = ed > ep ? ed : ep;
        if (eq > emax) emax = eq;
        k_fill3<<<cdiv(emax, 256), 256>>>(src_ddi, dst_ddi, ed,
                                          src_dpi, dst_dpi, ep,
                                          src_ppi, dst_ppi, eq);
    }

    // ---- layer 1: gather raw features (mean), then transform ----
    k_gather128<<<cdiv((long long)nd * 32, 256), 256>>>(0, x_drug, agg_ddi, nd);
    k_gather128<<<cdiv((long long)np * 32, 256), 256>>>(1, x_drug, agg_dpi, np);
    k_gather128<<<cdiv((long long)np * 32, 256), 256>>>(2, x_prot, agg_ppi, np);

    k_gemm1_single<<<cdiv(nd, 16), 128>>>(agg_ddi, W1_ddi, b1_ddi, h_d, nd);
    k_gemm1_dual<<<cdiv(np, 16), 128>>>(agg_dpi, W1_dpi, agg_ppi, W1_ppi,
                                        b1_dpi, b1_ppi, h_p, np);

    // ---- layer 2: transform first (64-dim payload), then fused gather+out ----
    k_gemm2_dual<<<cdiv(nd, 16), 128>>>(h_d, W2_ddi, W2_dpi, t_ddi, t_dpi, nd);
    k_gemm2_single<<<cdiv(np, 32), 128>>>(h_p, W2_ppi, t_ppi, np);

    k_out_drug<<<cdiv((long long)nd * 32, 256), 256>>>(t_ddi, b2_ddi, out, nd);
    k_out_prot<<<cdiv((long long)np * 32, 256), 256>>>(t_dpi, t_ppi, b2_dpi, b2_ppi,
                                                       out, nd, np);
}

// round 4
// speedup vs baseline: 2.3300x; 1.0228x over previous
#include <cuda_runtime.h>
#include <stdint.h>

#define NMAX 50000
#define EMAX 600000

typedef unsigned long long ull;

// ---------------- CSR scratch ----------------
__device__ int g_rowptr[3][NMAX + 1];
__device__ int g_cursor[3][NMAX];
__device__ int g_esrc[3][EMAX];

// ---------------- float scratch ----------------
constexpr size_t F_HD    = 0;                                  // [ND,128]
constexpr size_t F_HP    = F_HD    + (size_t)NMAX * 128;       // [NP,128]
constexpr size_t F_T_DDI = F_HP    + (size_t)NMAX * 128;       // [ND,64]
constexpr size_t F_T_DPI = F_T_DDI + (size_t)NMAX * 64;
constexpr size_t F_T_PPI = F_T_DPI + (size_t)NMAX * 64;
constexpr size_t F_TOTAL = F_T_PPI + (size_t)NMAX * 64;

__device__ float g_fs[F_TOTAL];

// ---------------- packed f32x2 helpers ----------------
__device__ __forceinline__ ull ffma2(ull a, ull b, ull c) {
    ull d;
    asm("fma.rn.f32x2 %0, %1, %2, %3;" : "=l"(d) : "l"(a), "l"(b), "l"(c));
    return d;
}
__device__ __forceinline__ ull pack2(float lo, float hi) {
    ull d;
    asm("mov.b64 %0, {%1, %2};" : "=l"(d) : "f"(lo), "f"(hi));
    return d;
}
__device__ __forceinline__ void unpack2(ull v, float& lo, float& hi) {
    asm("mov.b64 {%0, %1}, %2;" : "=f"(lo), "=f"(hi) : "l"(v));
}

// ---------------- CSR build ----------------

__global__ void k_zero_counts() {
    int i = blockIdx.x * blockDim.x + threadIdx.x;
    int total = 3 * (NMAX + 1);
    int stride = gridDim.x * blockDim.x;
    int* p = &g_rowptr[0][0];
    for (; i < total; i += stride) p[i] = 0;
}

__global__ void k_count(const int* __restrict__ d0, int e0,
                        const int* __restrict__ d1, int e1,
                        const int* __restrict__ d2, int e2) {
    int i = blockIdx.x * blockDim.x + threadIdx.x;
    int stride = gridDim.x * blockDim.x;
    for (int j = i; j < e0; j += stride) atomicAdd(&g_rowptr[0][__ldg(d0 + j)], 1);
    for (int j = i; j < e1; j += stride) atomicAdd(&g_rowptr[1][__ldg(d1 + j)], 1);
    for (int j = i; j < e2; j += stride) atomicAdd(&g_rowptr[2][__ldg(d2 + j)], 1);
}

__global__ void k_scan(int n0, int n1, int n2) {
    int rel = blockIdx.x;
    int n = (rel == 0) ? n0 : ((rel == 1) ? n1 : n2);
    int* cnt = g_rowptr[rel];
    int* cur = g_cursor[rel];
    __shared__ int sh[1024];
    int tid = threadIdx.x;
    int chunk = (n + 1023) >> 10;
    int lo = tid * chunk;
    int hi = lo + chunk;
    if (hi > n) hi = n;
    int tsum = 0;
    for (int i = lo; i < hi; i++) tsum += cnt[i];
    sh[tid] = tsum;
    __syncthreads();
    for (int off = 1; off < 1024; off <<= 1) {
        int v = (tid >= off) ? sh[tid - off] : 0;
        __syncthreads();
        sh[tid] += v;
        __syncthreads();
    }
    int run = (tid > 0) ? sh[tid - 1] : 0;
    for (int i = lo; i < hi; i++) {
        int c = cnt[i];
        cnt[i] = run;
        cur[i] = run;
        run += c;
    }
    if (tid == 0) cnt[n] = sh[1023];
}

__global__ void k_fill3(const int* __restrict__ s0, const int* __restrict__ d0, int e0,
                        const int* __restrict__ s1, const int* __restrict__ d1, int e1,
                        const int* __restrict__ s2, const int* __restrict__ d2, int e2) {
    int i = blockIdx.x * blockDim.x + threadIdx.x;
    int stride = gridDim.x * blockDim.x;
    for (int e = i; e < e0; e += stride) {
        int pos = atomicAdd(&g_cursor[0][__ldg(d0 + e)], 1);
        g_esrc[0][pos] = __ldg(s0 + e);
    }
    for (int e = i; e < e1; e += stride) {
        int pos = atomicAdd(&g_cursor[1][__ldg(d1 + e)], 1);
        g_esrc[1][pos] = __ldg(s1 + e);
    }
    for (int e = i; e < e2; e += stride) {
        int pos = atomicAdd(&g_cursor[2][__ldg(d2 + e)], 1);
        g_esrc[2][pos] = __ldg(s2 + e);
    }
}

// ---------------- gather primitives (unroll-8, atomic-free) ----------------

// 128-dim mean for `node` over rel CSR; lane covers dims [4l, 4l+4).
__device__ __forceinline__ float4 gather128_node(int rel, const float* __restrict__ x,
                                                 int node, int lane) {
    const int* ptr = g_rowptr[rel];
    const int* es = g_esrc[rel];
    int beg = ptr[node], end = ptr[node + 1];
    float4 a0 = make_float4(0.f, 0.f, 0.f, 0.f);
    float4 a1 = make_float4(0.f, 0.f, 0.f, 0.f);
    int e = beg;
    for (; e + 7 < end; e += 8) {
        int s[8];
#pragma unroll
        for (int j = 0; j < 8; j++) s[j] = __ldg(es + e + j);
        float4 v[8];
#pragma unroll
        for (int j = 0; j < 8; j++)
            v[j] = __ldg(reinterpret_cast<const float4*>(x + (size_t)s[j] * 128) + lane);
#pragma unroll
        for (int j = 0; j < 4; j++) {
            a0.x += v[j].x; a0.y += v[j].y; a0.z += v[j].z; a0.w += v[j].w;
            a1.x += v[j + 4].x; a1.y += v[j + 4].y;
            a1.z += v[j + 4].z; a1.w += v[j + 4].w;
        }
    }
    for (; e + 1 < end; e += 2) {
        int s0 = __ldg(es + e), s1 = __ldg(es + e + 1);
        float4 v0 = __ldg(reinterpret_cast<const float4*>(x + (size_t)s0 * 128) + lane);
        float4 v1 = __ldg(reinterpret_cast<const float4*>(x + (size_t)s1 * 128) + lane);
        a0.x += v0.x + v1.x; a0.y += v0.y + v1.y;
        a0.z += v0.z + v1.z; a0.w += v0.w + v1.w;
    }
    if (e < end) {
        int s = __ldg(es + e);
        float4 v = __ldg(reinterpret_cast<const float4*>(x + (size_t)s * 128) + lane);
        a0.x += v.x; a0.y += v.y; a0.z += v.z; a0.w += v.w;
    }
    float inv = 1.0f / fmaxf((float)(end - beg), 1.0f);
    return make_float4((a0.x + a1.x) * inv, (a0.y + a1.y) * inv,
                       (a0.z + a1.z) * inv, (a0.w + a1.w) * inv);
}

// 64-dim mean; lane covers dims (2l, 2l+1).
__device__ __forceinline__ float2 gather64_node(int rel, const float* __restrict__ x,
                                                int node, int lane) {
    const int* ptr = g_rowptr[rel];
    const int* es = g_esrc[rel];
    int beg = ptr[node], end = ptr[node + 1];
    float2 a0 = make_float2(0.f, 0.f);
    float2 a1 = make_float2(0.f, 0.f);
    int e = beg;
    for (; e + 7 < end; e += 8) {
        int s[8];
#pragma unroll
        for (int j = 0; j < 8; j++) s[j] = __ldg(es + e + j);
        float2 v[8];
#pragma unroll
        for (int j = 0; j < 8; j++)
            v[j] = __ldg(reinterpret_cast<const float2*>(x + (size_t)s[j] * 64) + lane);
#pragma unroll
        for (int j = 0; j < 4; j++) {
            a0.x += v[j].x; a0.y += v[j].y;
            a1.x += v[j + 4].x; a1.y += v[j + 4].y;
        }
    }
    for (; e + 1 < end; e += 2) {
        int s0 = __ldg(es + e), s1 = __ldg(es + e + 1);
        float2 v0 = __ldg(reinterpret_cast<const float2*>(x + (size_t)s0 * 64) + lane);
        float2 v1 = __ldg(reinterpret_cast<const float2*>(x + (size_t)s1 * 64) + lane);
        a0.x += v0.x + v1.x; a0.y += v0.y + v1.y;
    }
    if (e < end) {
        int s = __ldg(es + e);
        float2 v = __ldg(reinterpret_cast<const float2*>(x + (size_t)s * 64) + lane);
        a0.x += v.x; a0.y += v.y;
    }
    float inv = 1.0f / fmaxf((float)(end - beg), 1.0f);
    return make_float2((a0.x + a1.x) * inv, (a0.y + a1.y) * inv);
}

// ---------------- fused layer-1 kernels ----------------
// Block = 128 threads, 16 dst nodes. Phase 1: warp w gathers nodes 4w..4w+3
// into smem (k-paired float2 layout, conflict-free STS.128). Phase 2: f32x2
// GEMM from smem; acc pairs (k even, k odd), summed lo+hi at the end.

__global__ void __launch_bounds__(128)
k_l1_drug(const float* __restrict__ x,
          const float* __restrict__ W, const float* __restrict__ b,
          float* __restrict__ out, int n) {
    __shared__ float2 xs[16][64];
    int tid = threadIdx.x, wid = tid >> 5, lane = tid & 31;
    int row0 = blockIdx.x * 16;
#pragma unroll
    for (int i = 0; i < 4; i++) {
        int r = wid * 4 + i;
        int node = row0 + r;
        float4 m = make_float4(0.f, 0.f, 0.f, 0.f);
        if (node < n) m = gather128_node(0, x, node, lane);
        xs[r][2 * lane]     = make_float2(m.x, m.y);
        xs[r][2 * lane + 1] = make_float2(m.z, m.w);
    }
    __syncthreads();
    int j = tid;
    ull acc[16];
#pragma unroll
    for (int p = 0; p < 16; p++) acc[p] = 0ull;
    for (int kk = 0; kk < 64; kk++) {
        ull wv = pack2(__ldg(W + (2 * kk) * 128 + j), __ldg(W + (2 * kk + 1) * 128 + j));
#pragma unroll
        for (int p = 0; p < 16; p++) {
            ull xv = *reinterpret_cast<const ull*>(&xs[p][kk]);
            acc[p] = ffma2(xv, wv, acc[p]);
        }
    }
    float bb = __ldg(b + j);
#pragma unroll
    for (int p = 0; p < 16; p++) {
        float lo, hi;
        unpack2(acc[p], lo, hi);
        int r = row0 + p;
        if (r < n) out[(size_t)r * 128 + j] = lo + hi + bb;
    }
}

__global__ void __launch_bounds__(128)
k_l1_prot(const float* __restrict__ xd, const float* __restrict__ xp,
          const float* __restrict__ W1, const float* __restrict__ W2,
          const float* __restrict__ b1, const float* __restrict__ b2,
          float* __restrict__ out, int n) {
    __shared__ float2 xs1[16][64];
    __shared__ float2 xs2[16][64];
    int tid = threadIdx.x, wid = tid >> 5, lane = tid & 31;
    int row0 = blockIdx.x * 16;
#pragma unroll
    for (int i = 0; i < 4; i++) {
        int r = wid * 4 + i;
        int node = row0 + r;
        float4 m1 = make_float4(0.f, 0.f, 0.f, 0.f);
        float4 m2 = make_float4(0.f, 0.f, 0.f, 0.f);
        if (node < n) {
            m1 = gather128_node(1, xd, node, lane);
            m2 = gather128_node(2, xp, node, lane);
        }
        xs1[r][2 * lane]     = make_float2(m1.x, m1.y);
        xs1[r][2 * lane + 1] = make_float2(m1.z, m1.w);
        xs2[r][2 * lane]     = make_float2(m2.x, m2.y);
        xs2[r][2 * lane + 1] = make_float2(m2.z, m2.w);
    }
    __syncthreads();
    int j = tid;
    ull acc[16];
#pragma unroll
    for (int p = 0; p < 16; p++) acc[p] = 0ull;
    for (int kk = 0; kk < 64; kk++) {
        ull wv1 = pack2(__ldg(W1 + (2 * kk) * 128 + j), __ldg(W1 + (2 * kk + 1) * 128 + j));
        ull wv2 = pack2(__ldg(W2 + (2 * kk) * 128 + j), __ldg(W2 + (2 * kk + 1) * 128 + j));
#pragma unroll
        for (int p = 0; p < 16; p++) {
            acc[p] = ffma2(*reinterpret_cast<const ull*>(&xs1[p][kk]), wv1, acc[p]);
            acc[p] = ffma2(*reinterpret_cast<const ull*>(&xs2[p][kk]), wv2, acc[p]);
        }
    }
    float bb = __ldg(b1 + j) + __ldg(b2 + j);
#pragma unroll
    for (int p = 0; p < 16; p++) {
        float lo, hi;
        unpack2(acc[p], lo, hi);
        int r = row0 + p;
        if (r < n) out[(size_t)r * 128 + j] = lo + hi + bb;
    }
}

// ---------------- layer-2 GEMMs (row-paired f32x2, from round 3) ----------------

__global__ void k_gemm2_dual(const float* __restrict__ H,
                             const float* __restrict__ Wa,
                             const float* __restrict__ Wb,
                             float* __restrict__ ta,
                             float* __restrict__ tb, int n) {
    __shared__ float2 xs[128][9];
    int tid = threadIdx.x;
    int row0 = blockIdx.x * 16;
#pragma unroll
    for (int p = 0; p < 8; p++) {
        int r0 = row0 + p, r1 = row0 + p + 8;
        float v0 = (r0 < n) ? H[(size_t)r0 * 128 + tid] : 0.f;
        float v1 = (r1 < n) ? H[(size_t)r1 * 128 + tid] : 0.f;
        xs[tid][p] = make_float2(v0, v1);
    }
    __syncthreads();
    const float* W = (tid < 64) ? Wa : Wb;
    float* o = (tid < 64) ? ta : tb;
    int c = tid & 63;
    ull acc[8];
#pragma unroll
    for (int p = 0; p < 8; p++) acc[p] = 0ull;
    for (int k = 0; k < 128; k++) {
        float wv = __ldg(W + k * 64 + c);
        ull wv2 = pack2(wv, wv);
        const ull* row = reinterpret_cast<const ull*>(&xs[k][0]);
#pragma unroll
        for (int p = 0; p < 8; p++) acc[p] = ffma2(row[p], wv2, acc[p]);
    }
#pragma unroll
    for (int p = 0; p < 8; p++) {
        float lo, hi;
        unpack2(acc[p], lo, hi);
        int r0 = row0 + p, r1 = row0 + p + 8;
        if (r0 < n) o[(size_t)r0 * 64 + c] = lo;
        if (r1 < n) o[(size_t)r1 * 64 + c] = hi;
    }
}

__global__ void k_gemm2_single(const float* __restrict__ H,
                               const float* __restrict__ W,
                               float* __restrict__ t, int n) {
    __shared__ float2 xs[128][2][9];
    int tid = threadIdx.x;
    int row0 = blockIdx.x * 32;
#pragma unroll
    for (int g = 0; g < 2; g++) {
#pragma unroll
        for (int p = 0; p < 8; p++) {
            int r0 = row0 + g * 16 + p, r1 = row0 + g * 16 + p + 8;
            float v0 = (r0 < n) ? H[(size_t)r0 * 128 + tid] : 0.f;
            float v1 = (r1 < n) ? H[(size_t)r1 * 128 + tid] : 0.f;
            xs[tid][g][p] = make_float2(v0, v1);
        }
    }
    __syncthreads();
    int g = tid >> 6;
    int c = tid & 63;
    ull acc[8];
#pragma unroll
    for (int p = 0; p < 8; p++) acc[p] = 0ull;
    for (int k = 0; k < 128; k++) {
        float wv = __ldg(W + k * 64 + c);
        ull wv2 = pack2(wv, wv);
        const ull* row = reinterpret_cast<const ull*>(&xs[k][g][0]);
#pragma unroll
        for (int p = 0; p < 8; p++) acc[p] = ffma2(row[p], wv2, acc[p]);
    }
#pragma unroll
    for (int p = 0; p < 8; p++) {
        float lo, hi;
        unpack2(acc[p], lo, hi);
        int r0 = row0 + g * 16 + p, r1 = row0 + g * 16 + p + 8;
        if (r0 < n) t[(size_t)r0 * 64 + c] = lo;
        if (r1 < n) t[(size_t)r1 * 64 + c] = hi;
    }
}

// ---------------- fused layer-2 gather + bias + concat ----------------

__global__ void k_out_drug(const float* __restrict__ t_ddi,
                           const float* __restrict__ b2_ddi,
                           float* __restrict__ out, int nd) {
    int t = blockIdx.x * blockDim.x + threadIdx.x;
    int node = t >> 5;
    if (node >= nd) return;
    int lane = t & 31;
    float2 m = gather64_node(0, t_ddi, node, lane);
    float2 bb = __ldg(reinterpret_cast<const float2*>(b2_ddi) + lane);
    *(reinterpret_cast<float2*>(out + (size_t)node * 64) + lane) =
        make_float2(m.x + bb.x, m.y + bb.y);
}

__global__ void k_out_prot(const float* __restrict__ t_dpi,
                           const float* __restrict__ t_ppi,
                           const float* __restrict__ b2_dpi,
                           const float* __restrict__ b2_ppi,
                           float* __restrict__ out, int nd, int np) {
    int t = blockIdx.x * blockDim.x + threadIdx.x;
    int node = t >> 5;
    if (node >= np) return;
    int lane = t & 31;
    float2 m1 = gather64_node(1, t_dpi, node, lane);
    float2 m2 = gather64_node(2, t_ppi, node, lane);
    float2 ba = __ldg(reinterpret_cast<const float2*>(b2_dpi) + lane);
    float2 bb = __ldg(reinterpret_cast<const float2*>(b2_ppi) + lane);
    *(reinterpret_cast<float2*>(out + (size_t)(nd + node) * 64) + lane) =
        make_float2(m1.x + m2.x + ba.x + bb.x, m1.y + m2.y + ba.y + bb.y);
}

// ---------------- host launcher ----------------

static float* fs_ptr() {
    static float* p = nullptr;
    if (!p) cudaGetSymbolAddress((void**)&p, g_fs);
    return p;
}

static inline int cdiv(long long a, long long b) { return (int)((a + b - 1) / b); }

extern "C" void kernel_launch(void* const* d_in, const int* in_sizes, int n_in,
                              void* d_out, int out_size) {
    const float* x_drug = (const float*)d_in[0];
    const float* x_prot = (const float*)d_in[1];
    const int* src_ddi = (const int*)d_in[2];
    const int* dst_ddi = (const int*)d_in[3];
    const int* src_dpi = (const int*)d_in[4];
    const int* dst_dpi = (const int*)d_in[5];
    const int* src_ppi = (const int*)d_in[6];
    const int* dst_ppi = (const int*)d_in[7];
    const float* W1_ddi = (const float*)d_in[8];
    const float* b1_ddi = (const float*)d_in[9];
    const float* W1_dpi = (const float*)d_in[10];
    const float* b1_dpi = (const float*)d_in[11];
    const float* W1_ppi = (const float*)d_in[12];
    const float* b1_ppi = (const float*)d_in[13];
    const float* W2_ddi = (const float*)d_in[14];
    const float* b2_ddi = (const float*)d_in[15];
    const float* W2_dpi = (const float*)d_in[16];
    const float* b2_dpi = (const float*)d_in[17];
    const float* W2_ppi = (const float*)d_in[18];
    const float* b2_ppi = (const float*)d_in[19];
    float* out = (float*)d_out;

    int nd = in_sizes[0] / 128;
    int np = in_sizes[1] / 128;
    int ed = in_sizes[2];
    int ep = in_sizes[4];
    int eq = in_sizes[6];

    float* S = fs_ptr();
    float* h_d   = S + F_HD;
    float* h_p   = S + F_HP;
    float* t_ddi = S + F_T_DDI;
    float* t_dpi = S + F_T_DPI;
    float* t_ppi = S + F_T_PPI;

    // ---- CSR build (shared by both layers) ----
    k_zero_counts<<<cdiv(3 * (NMAX + 1), 256), 256>>>();
    {
        int emax = ed > ep ? ed : ep;
        if (eq > emax) emax = eq;
        k_count<<<cdiv(emax, 256), 256>>>(dst_ddi, ed, dst_dpi, ep, dst_ppi, eq);
    }
    k_scan<<<3, 1024>>>(nd, np, np);
    {
        int emax = ed > ep ? ed : ep;
        if (eq > emax) emax = eq;
        k_fill3<<<cdiv(emax, 256), 256>>>(src_ddi, dst_ddi, ed,
                                          src_dpi, dst_dpi, ep,
                                          src_ppi, dst_ppi, eq);
    }

    // ---- layer 1: fused gather + GEMM ----
    k_l1_drug<<<cdiv(nd, 16), 128>>>(x_drug, W1_ddi, b1_ddi, h_d, nd);
    k_l1_prot<<<cdiv(np, 16), 128>>>(x_drug, x_prot, W1_dpi, W1_ppi,
                                     b1_dpi, b1_ppi, h_p, np);

    // ---- layer 2: transform (64-dim payload), then fused gather + out ----
    k_gemm2_dual<<<cdiv(nd, 16), 128>>>(h_d, W2_ddi, W2_dpi, t_ddi, t_dpi, nd);
    k_gemm2_single<<<cdiv(np, 32), 128>>>(h_p, W2_ppi, t_ppi, np);

    k_out_drug<<<cdiv((long long)nd * 32, 256), 256>>>(t_ddi, b2_ddi, out, nd);
    k_out_prot<<<cdiv((long long)np * 32, 256), 256>>>(t_dpi, t_ppi, b2_dpi, b2_ppi,
                                                       out, nd, np);
}

// round 5
// speedup vs baseline: 2.4574x; 1.0547x over previous
#include <cuda_runtime.h>
#include <stdint.h>

#define NMAX 50000
#define EMAX 600000

typedef unsigned long long ull;

// ---------------- CSR scratch ----------------
__device__ int g_rowptr[3][NMAX + 1];
__device__ int g_cursor[3][NMAX];
__device__ int g_esrc[3][EMAX];

// ---------------- float scratch ----------------
constexpr size_t F_HD    = 0;                                  // [ND,128]
constexpr size_t F_HP    = F_HD    + (size_t)NMAX * 128;       // [NP,128]
constexpr size_t F_T_DDI = F_HP    + (size_t)NMAX * 128;       // [ND,64]
constexpr size_t F_T_DPI = F_T_DDI + (size_t)NMAX * 64;
constexpr size_t F_T_PPI = F_T_DPI + (size_t)NMAX * 64;
constexpr size_t F_TOTAL = F_T_PPI + (size_t)NMAX * 64;

__device__ float g_fs[F_TOTAL];

// ---------------- packed f32x2 helpers ----------------
__device__ __forceinline__ ull ffma2(ull a, ull b, ull c) {
    ull d;
    asm("fma.rn.f32x2 %0, %1, %2, %3;" : "=l"(d) : "l"(a), "l"(b), "l"(c));
    return d;
}
__device__ __forceinline__ ull pack2(float lo, float hi) {
    ull d;
    asm("mov.b64 %0, {%1, %2};" : "=l"(d) : "f"(lo), "f"(hi));
    return d;
}
__device__ __forceinline__ void unpack2(ull v, float& lo, float& hi) {
    asm("mov.b64 {%0, %1}, %2;" : "=f"(lo), "=f"(hi) : "l"(v));
}

// ---------------- CSR build ----------------

__global__ void k_zero_counts() {
    int i = blockIdx.x * blockDim.x + threadIdx.x;
    int total = 3 * (NMAX + 1);
    int stride = gridDim.x * blockDim.x;
    int* p = &g_rowptr[0][0];
    for (; i < total; i += stride) p[i] = 0;
}

__global__ void k_count(const int* __restrict__ d0, int e0,
                        const int* __restrict__ d1, int e1,
                        const int* __restrict__ d2, int e2) {
    int i = blockIdx.x * blockDim.x + threadIdx.x;
    int stride = gridDim.x * blockDim.x;
    for (int j = i; j < e0; j += stride) atomicAdd(&g_rowptr[0][__ldg(d0 + j)], 1);
    for (int j = i; j < e1; j += stride) atomicAdd(&g_rowptr[1][__ldg(d1 + j)], 1);
    for (int j = i; j < e2; j += stride) atomicAdd(&g_rowptr[2][__ldg(d2 + j)], 1);
}

__global__ void k_scan(int n0, int n1, int n2) {
    int rel = blockIdx.x;
    int n = (rel == 0) ? n0 : ((rel == 1) ? n1 : n2);
    int* cnt = g_rowptr[rel];
    int* cur = g_cursor[rel];
    __shared__ int sh[1024];
    int tid = threadIdx.x;
    int chunk = (n + 1023) >> 10;
    int lo = tid * chunk;
    int hi = lo + chunk;
    if (hi > n) hi = n;
    int tsum = 0;
    for (int i = lo; i < hi; i++) tsum += cnt[i];
    sh[tid] = tsum;
    __syncthreads();
    for (int off = 1; off < 1024; off <<= 1) {
        int v = (tid >= off) ? sh[tid - off] : 0;
        __syncthreads();
        sh[tid] += v;
        __syncthreads();
    }
    int run = (tid > 0) ? sh[tid - 1] : 0;
    for (int i = lo; i < hi; i++) {
        int c = cnt[i];
        cnt[i] = run;
        cur[i] = run;
        run += c;
    }
    if (tid == 0) cnt[n] = sh[1023];
}

__global__ void k_fill3(const int* __restrict__ s0, const int* __restrict__ d0, int e0,
                        const int* __restrict__ s1, const int* __restrict__ d1, int e1,
                        const int* __restrict__ s2, const int* __restrict__ d2, int e2) {
    int i = blockIdx.x * blockDim.x + threadIdx.x;
    int stride = gridDim.x * blockDim.x;
    for (int e = i; e < e0; e += stride) {
        int pos = atomicAdd(&g_cursor[0][__ldg(d0 + e)], 1);
        g_esrc[0][pos] = __ldg(s0 + e);
    }
    for (int e = i; e < e1; e += stride) {
        int pos = atomicAdd(&g_cursor[1][__ldg(d1 + e)], 1);
        g_esrc[1][pos] = __ldg(s1 + e);
    }
    for (int e = i; e < e2; e += stride) {
        int pos = atomicAdd(&g_cursor[2][__ldg(d2 + e)], 1);
        g_esrc[2][pos] = __ldg(s2 + e);
    }
}

// ---------------- pair-interleaved gather primitives ----------------
// Two nodes per warp, predicated unroll-4 over max(deg) -> up to 8
// independent row loads in flight for the entire loop (tails included).

__device__ __forceinline__ void gpair128(const int* __restrict__ es,
                                         const float* __restrict__ x,
                                         int b0, int d0, int b1, int d1, int lane,
                                         float4& o0, float4& o1) {
    float4 a0 = make_float4(0.f, 0.f, 0.f, 0.f);
    float4 a1 = make_float4(0.f, 0.f, 0.f, 0.f);
    int m = d0 > d1 ? d0 : d1;
    for (int e = 0; e < m; e += 4) {
        float4 v0[4], v1[4];
#pragma unroll
        for (int j = 0; j < 4; j++) {
            bool q0 = (e + j) < d0;
            bool q1 = (e + j) < d1;
            int s0 = q0 ? __ldg(es + b0 + e + j) : 0;
            int s1 = q1 ? __ldg(es + b1 + e + j) : 0;
            v0[j] = q0 ? __ldg(reinterpret_cast<const float4*>(x + (size_t)s0 * 128) + lane)
                       : make_float4(0.f, 0.f, 0.f, 0.f);
            v1[j] = q1 ? __ldg(reinterpret_cast<const float4*>(x + (size_t)s1 * 128) + lane)
                       : make_float4(0.f, 0.f, 0.f, 0.f);
        }
#pragma unroll
        for (int j = 0; j < 4; j++) {
            a0.x += v0[j].x; a0.y += v0[j].y; a0.z += v0[j].z; a0.w += v0[j].w;
            a1.x += v1[j].x; a1.y += v1[j].y; a1.z += v1[j].z; a1.w += v1[j].w;
        }
    }
    float i0 = 1.0f / fmaxf((float)d0, 1.0f);
    float i1 = 1.0f / fmaxf((float)d1, 1.0f);
    o0 = make_float4(a0.x * i0, a0.y * i0, a0.z * i0, a0.w * i0);
    o1 = make_float4(a1.x * i1, a1.y * i1, a1.z * i1, a1.w * i1);
}

__device__ __forceinline__ void gpair64(const int* __restrict__ es,
                                        const float* __restrict__ x,
                                        int b0, int d0, int b1, int d1, int lane,
                                        float2& o0, float2& o1) {
    float2 a0 = make_float2(0.f, 0.f);
    float2 a1 = make_float2(0.f, 0.f);
    int m = d0 > d1 ? d0 : d1;
    for (int e = 0; e < m; e += 4) {
        float2 v0[4], v1[4];
#pragma unroll
        for (int j = 0; j < 4; j++) {
            bool q0 = (e + j) < d0;
            bool q1 = (e + j) < d1;
            int s0 = q0 ? __ldg(es + b0 + e + j) : 0;
            int s1 = q1 ? __ldg(es + b1 + e + j) : 0;
            v0[j] = q0 ? __ldg(reinterpret_cast<const float2*>(x + (size_t)s0 * 64) + lane)
                       : make_float2(0.f, 0.f);
            v1[j] = q1 ? __ldg(reinterpret_cast<const float2*>(x + (size_t)s1 * 64) + lane)
                       : make_float2(0.f, 0.f);
        }
#pragma unroll
        for (int j = 0; j < 4; j++) {
            a0.x += v0[j].x; a0.y += v0[j].y;
            a1.x += v1[j].x; a1.y += v1[j].y;
        }
    }
    float i0 = 1.0f / fmaxf((float)d0, 1.0f);
    float i1 = 1.0f / fmaxf((float)d1, 1.0f);
    o0 = make_float2(a0.x * i0, a0.y * i0);
    o1 = make_float2(a1.x * i1, a1.y * i1);
}

// helper: (beg, deg) with validity clamp
__device__ __forceinline__ void node_range(const int* __restrict__ ptr, int node, int n,
                                           int& b, int& d) {
    if (node < n) {
        b = ptr[node];
        d = ptr[node + 1] - b;
    } else {
        b = 0; d = 0;
    }
}

// ---------------- merged fused layer-1 ----------------
// 256 threads, 16 dst rows per block. Gather: warp w -> local rows 2w, 2w+1
// (pair-interleaved). GEMM: j = tid&127, half = tid>>7 handles 8 rows.
// Blocks [0, nbd) -> drug (rel 0); blocks [nbd, ...) -> protein (rels 1+2).

__global__ void __launch_bounds__(256, 3)
k_l1(const float* __restrict__ xd, const float* __restrict__ xp,
     const float* __restrict__ W1_ddi, const float* __restrict__ b1_ddi,
     const float* __restrict__ W1_dpi, const float* __restrict__ b1_dpi,
     const float* __restrict__ W1_ppi, const float* __restrict__ b1_ppi,
     float* __restrict__ h_d, float* __restrict__ h_p,
     int nd, int np, int nbd) {
    __shared__ float2 xs1[16][64];
    __shared__ float2 xs2[16][64];
    int tid = threadIdx.x, wid = tid >> 5, lane = tid & 31;
    bool drug = (int)blockIdx.x < nbd;
    int row0 = (drug ? blockIdx.x : blockIdx.x - nbd) * 16;
    int n = drug ? nd : np;

    int r0 = wid * 2, r1 = r0 + 1;
    int node0 = row0 + r0, node1 = row0 + r1;

    if (drug) {
        int b0, d0, b1, d1;
        node_range(g_rowptr[0], node0, n, b0, d0);
        node_range(g_rowptr[0], node1, n, b1, d1);
        float4 m0, m1;
        gpair128(g_esrc[0], xd, b0, d0, b1, d1, lane, m0, m1);
        xs1[r0][2 * lane]     = make_float2(m0.x, m0.y);
        xs1[r0][2 * lane + 1] = make_float2(m0.z, m0.w);
        xs1[r1][2 * lane]     = make_float2(m1.x, m1.y);
        xs1[r1][2 * lane + 1] = make_float2(m1.z, m1.w);
    } else {
        int b0, d0, b1, d1;
        node_range(g_rowptr[1], node0, n, b0, d0);
        node_range(g_rowptr[1], node1, n, b1, d1);
        float4 m0, m1;
        gpair128(g_esrc[1], xd, b0, d0, b1, d1, lane, m0, m1);
        xs1[r0][2 * lane]     = make_float2(m0.x, m0.y);
        xs1[r0][2 * lane + 1] = make_float2(m0.z, m0.w);
        xs1[r1][2 * lane]     = make_float2(m1.x, m1.y);
        xs1[r1][2 * lane + 1] = make_float2(m1.z, m1.w);

        node_range(g_rowptr[2], node0, n, b0, d0);
        node_range(g_rowptr[2], node1, n, b1, d1);
        gpair128(g_esrc[2], xp, b0, d0, b1, d1, lane, m0, m1);
        xs2[r0][2 * lane]     = make_float2(m0.x, m0.y);
        xs2[r0][2 * lane + 1] = make_float2(m0.z, m0.w);
        xs2[r1][2 * lane]     = make_float2(m1.x, m1.y);
        xs2[r1][2 * lane + 1] = make_float2(m1.z, m1.w);
    }
    __syncthreads();

    int j = tid & 127;
    int half = tid >> 7;
    int rbase = half * 8;
    ull acc[8];
#pragma unroll
    for (int p = 0; p < 8; p++) acc[p] = 0ull;

    if (drug) {
        for (int kk = 0; kk < 64; kk++) {
            ull wv = pack2(__ldg(W1_ddi + (2 * kk) * 128 + j),
                           __ldg(W1_ddi + (2 * kk + 1) * 128 + j));
#pragma unroll
            for (int p = 0; p < 8; p++)
                acc[p] = ffma2(*reinterpret_cast<const ull*>(&xs1[rbase + p][kk]), wv, acc[p]);
        }
        float bb = __ldg(b1_ddi + j);
#pragma unroll
        for (int p = 0; p < 8; p++) {
            float lo, hi;
            unpack2(acc[p], lo, hi);
            int r = row0 + rbase + p;
            if (r < n) h_d[(size_t)r * 128 + j] = lo + hi + bb;
        }
    } else {
        for (int kk = 0; kk < 64; kk++) {
            ull wv1 = pack2(__ldg(W1_dpi + (2 * kk) * 128 + j),
                            __ldg(W1_dpi + (2 * kk + 1) * 128 + j));
            ull wv2 = pack2(__ldg(W1_ppi + (2 * kk) * 128 + j),
                            __ldg(W1_ppi + (2 * kk + 1) * 128 + j));
#pragma unroll
            for (int p = 0; p < 8; p++) {
                acc[p] = ffma2(*reinterpret_cast<const ull*>(&xs1[rbase + p][kk]), wv1, acc[p]);
                acc[p] = ffma2(*reinterpret_cast<const ull*>(&xs2[rbase + p][kk]), wv2, acc[p]);
            }
        }
        float bb = __ldg(b1_dpi + j) + __ldg(b1_ppi + j);
#pragma unroll
        for (int p = 0; p < 8; p++) {
            float lo, hi;
            unpack2(acc[p], lo, hi);
            int r = row0 + rbase + p;
            if (r < n) h_p[(size_t)r * 128 + j] = lo + hi + bb;
        }
    }
}

// ---------------- merged layer-2 GEMM ----------------
// Blocks [0, nbd): drug — 16 rows of h_d, dual output (t_ddi | t_dpi).
// Blocks [nbd, ...): prot — 32 rows of h_p, single output (t_ppi).

__global__ void __launch_bounds__(128)
k_gemm2(const float* __restrict__ h_d, const float* __restrict__ h_p,
        const float* __restrict__ W2_ddi, const float* __restrict__ W2_dpi,
        const float* __restrict__ W2_ppi,
        float* __restrict__ t_ddi, float* __restrict__ t_dpi,
        float* __restrict__ t_ppi, int nd, int np, int nbd) {
    __shared__ float2 xs[128][2][9];
    int tid = threadIdx.x;
    bool drug = (int)blockIdx.x < nbd;

    if (drug) {
        int row0 = blockIdx.x * 16;
#pragma unroll
        for (int p = 0; p < 8; p++) {
            int r0 = row0 + p, r1 = row0 + p + 8;
            float v0 = (r0 < nd) ? h_d[(size_t)r0 * 128 + tid] : 0.f;
            float v1 = (r1 < nd) ? h_d[(size_t)r1 * 128 + tid] : 0.f;
            xs[tid][0][p] = make_float2(v0, v1);
        }
        __syncthreads();
        const float* W = (tid < 64) ? W2_ddi : W2_dpi;
        float* o = (tid < 64) ? t_ddi : t_dpi;
        int c = tid & 63;
        ull acc[8];
#pragma unroll
        for (int p = 0; p < 8; p++) acc[p] = 0ull;
        for (int k = 0; k < 128; k++) {
            float wv = __ldg(W + k * 64 + c);
            ull wv2 = pack2(wv, wv);
            const ull* row = reinterpret_cast<const ull*>(&xs[k][0][0]);
#pragma unroll
            for (int p = 0; p < 8; p++) acc[p] = ffma2(row[p], wv2, acc[p]);
        }
#pragma unroll
        for (int p = 0; p < 8; p++) {
            float lo, hi;
            unpack2(acc[p], lo, hi);
            int r0 = row0 + p, r1 = row0 + p + 8;
            if (r0 < nd) o[(size_t)r0 * 64 + c] = lo;
            if (r1 < nd) o[(size_t)r1 * 64 + c] = hi;
        }
    } else {
        int row0 = (blockIdx.x - nbd) * 32;
#pragma unroll
        for (int g = 0; g < 2; g++) {
#pragma unroll
            for (int p = 0; p < 8; p++) {
                int r0 = row0 + g * 16 + p, r1 = row0 + g * 16 + p + 8;
                float v0 = (r0 < np) ? h_p[(size_t)r0 * 128 + tid] : 0.f;
                float v1 = (r1 < np) ? h_p[(size_t)r1 * 128 + tid] : 0.f;
                xs[tid][g][p] = make_float2(v0, v1);
            }
        }
        __syncthreads();
        int g = tid >> 6;
        int c = tid & 63;
        ull acc[8];
#pragma unroll
        for (int p = 0; p < 8; p++) acc[p] = 0ull;
        for (int k = 0; k < 128; k++) {
            float wv = __ldg(W2_ppi + k * 64 + c);
            ull wv2 = pack2(wv, wv);
            const ull* row = reinterpret_cast<const ull*>(&xs[k][g][0]);
#pragma unroll
            for (int p = 0; p < 8; p++) acc[p] = ffma2(row[p], wv2, acc[p]);
        }
#pragma unroll
        for (int p = 0; p < 8; p++) {
            float lo, hi;
            unpack2(acc[p], lo, hi);
            int r0 = row0 + g * 16 + p, r1 = row0 + g * 16 + p + 8;
            if (r0 < np) t_ppi[(size_t)r0 * 64 + c] = lo;
            if (r1 < np) t_ppi[(size_t)r1 * 64 + c] = hi;
        }
    }
}

// ---------------- merged layer-2 gather + bias + concat ----------------
// 256 threads = 8 warps; each warp handles 2 nodes (pair-interleaved gather).
// Warps [0, wd) -> drug; warps [wd, wd+wp) -> protein.

__global__ void __launch_bounds__(256)
k_out(const float* __restrict__ t_ddi, const float* __restrict__ t_dpi,
      const float* __restrict__ t_ppi,
      const float* __restrict__ b2_ddi, const float* __restrict__ b2_dpi,
      const float* __restrict__ b2_ppi,
      float* __restrict__ out, int nd, int np, int wd) {
    int gw = blockIdx.x * 8 + (threadIdx.x >> 5);
    int lane = threadIdx.x & 31;
    if (gw < wd) {
        int node0 = gw * 2, node1 = node0 + 1;
        int b0, d0, b1, d1;
        node_range(g_rowptr[0], node0, nd, b0, d0);
        node_range(g_rowptr[0], node1, nd, b1, d1);
        float2 m0, m1;
        gpair64(g_esrc[0], t_ddi, b0, d0, b1, d1, lane, m0, m1);
        float2 bb = __ldg(reinterpret_cast<const float2*>(b2_ddi) + lane);
        if (node0 < nd)
            *(reinterpret_cast<float2*>(out + (size_t)node0 * 64) + lane) =
                make_float2(m0.x + bb.x, m0.y + bb.y);
        if (node1 < nd)
            *(reinterpret_cast<float2*>(out + (size_t)node1 * 64) + lane) =
                make_float2(m1.x + bb.x, m1.y + bb.y);
    } else {
        int node0 = (gw - wd) * 2, node1 = node0 + 1;
        int b0, d0, b1, d1;
        node_range(g_rowptr[1], node0, np, b0, d0);
        node_range(g_rowptr[1], node1, np, b1, d1);
        float2 ma0, ma1;
        gpair64(g_esrc[1], t_dpi, b0, d0, b1, d1, lane, ma0, ma1);
        node_range(g_rowptr[2], node0, np, b0, d0);
        node_range(g_rowptr[2], node1, np, b1, d1);
        float2 mb0, mb1;
        gpair64(g_esrc[2], t_ppi, b0, d0, b1, d1, lane, mb0, mb1);
        float2 ba = __ldg(reinterpret_cast<const float2*>(b2_dpi) + lane);
        float2 bb = __ldg(reinterpret_cast<const float2*>(b2_ppi) + lane);
        float bx = ba.x + bb.x, by = ba.y + bb.y;
        if (node0 < np)
            *(reinterpret_cast<float2*>(out + (size_t)(nd + node0) * 64) + lane) =
                make_float2(ma0.x + mb0.x + bx, ma0.y + mb0.y + by);
        if (node1 < np)
            *(reinterpret_cast<float2*>(out + (size_t)(nd + node1) * 64) + lane) =
                make_float2(ma1.x + mb1.x + bx, ma1.y + mb1.y + by);
    }
}

// ---------------- host launcher ----------------

static float* fs_ptr() {
    static float* p = nullptr;
    if (!p) cudaGetSymbolAddress((void**)&p, g_fs);
    return p;
}

static inline int cdiv(long long a, long long b) { return (int)((a + b - 1) / b); }

extern "C" void kernel_launch(void* const* d_in, const int* in_sizes, int n_in,
                              void* d_out, int out_size) {
    const float* x_drug = (const float*)d_in[0];
    const float* x_prot = (const float*)d_in[1];
    const int* src_ddi = (const int*)d_in[2];
    const int* dst_ddi = (const int*)d_in[3];
    const int* src_dpi = (const int*)d_in[4];
    const int* dst_dpi = (const int*)d_in[5];
    const int* src_ppi = (const int*)d_in[6];
    const int* dst_ppi = (const int*)d_in[7];
    const float* W1_ddi = (const float*)d_in[8];
    const float* b1_ddi = (const float*)d_in[9];
    const float* W1_dpi = (const float*)d_in[10];
    const float* b1_dpi = (const float*)d_in[11];
    const float* W1_ppi = (const float*)d_in[12];
    const float* b1_ppi = (const float*)d_in[13];
    const float* W2_ddi = (const float*)d_in[14];
    const float* b2_ddi = (const float*)d_in[15];
    const float* W2_dpi = (const float*)d_in[16];
    const float* b2_dpi = (const float*)d_in[17];
    const float* W2_ppi = (const float*)d_in[18];
    const float* b2_ppi = (const float*)d_in[19];
    float* out = (float*)d_out;

    int nd = in_sizes[0] / 128;
    int np = in_sizes[1] / 128;
    int ed = in_sizes[2];
    int ep = in_sizes[4];
    int eq = in_sizes[6];

    float* S = fs_ptr();
    float* h_d   = S + F_HD;
    float* h_p   = S + F_HP;
    float* t_ddi = S + F_T_DDI;
    float* t_dpi = S + F_T_DPI;
    float* t_ppi = S + F_T_PPI;

    // ---- CSR build ----
    k_zero_counts<<<cdiv(3 * (NMAX + 1), 256), 256>>>();
    int emax = ed > ep ? ed : ep;
    if (eq > emax) emax = eq;
    k_count<<<cdiv(emax, 256), 256>>>(dst_ddi, ed, dst_dpi, ep, dst_ppi, eq);
    k_scan<<<3, 1024>>>(nd, np, np);
    k_fill3<<<cdiv(emax, 256), 256>>>(src_ddi, dst_ddi, ed,
                                      src_dpi, dst_dpi, ep,
                                      src_ppi, dst_ppi, eq);

    // ---- layer 1: fused gather + GEMM (drug and protein in one launch) ----
    int nbd1 = cdiv(nd, 16), nbp1 = cdiv(np, 16);
    k_l1<<<nbd1 + nbp1, 256>>>(x_drug, x_prot,
                               W1_ddi, b1_ddi, W1_dpi, b1_dpi, W1_ppi, b1_ppi,
                               h_d, h_p, nd, np, nbd1);

    // ---- layer 2 transforms (one launch) ----
    int nbd2 = cdiv(nd, 16), nbp2 = cdiv(np, 32);
    k_gemm2<<<nbd2 + nbp2, 128>>>(h_d, h_p, W2_ddi, W2_dpi, W2_ppi,
                                  t_ddi, t_dpi, t_ppi, nd, np, nbd2);

    // ---- layer 2 gather + bias + concat (one launch) ----
    int wd = cdiv(nd, 2), wp = cdiv(np, 2);
    k_out<<<cdiv(wd + wp, 8), 256>>>(t_ddi, t_dpi, t_ppi,
                                     b2_ddi, b2_dpi, b2_ppi, out, nd, np, wd);
}